// round 10
// baseline (speedup 1.0000x reference)
#include <cuda_runtime.h>
#include <cuda_fp16.h>
#include <math.h>
#include <stdint.h>

// ---------------------------------------------------------------------------
// Problem constants
// ---------------------------------------------------------------------------
#define BB   2
#define TT   2048
#define DD   1024
#define HH   16
#define HDIM 4096
#define VV   32000
#define LL   4
#define MM   (BB*TT)      // 4096 rows
#define QKVD (3*DD)       // 3072

// ---------------------------------------------------------------------------
// Static device scratch (no allocations allowed)
// ---------------------------------------------------------------------------
__device__ float g_x  [MM*DD];
__device__ __half g_qkvh[MM*QKVD], g_qkvl[MM*QKVD];
__device__ __half g_xnh[MM*DD],  g_xnl[MM*DD];
__device__ __half g_yh [MM*DD],  g_yl [MM*DD];
__device__ __half g_hh [MM*HDIM], g_hl [MM*HDIM];
__device__ __half g_xh [MM*DD],  g_xl [MM*DD];
// single-term fp16 weights (recomputed every launch — weights are inputs)
__device__ __half g_wqkv[LL*QKVD*DD];
__device__ __half g_wo  [LL*DD*DD];
__device__ __half g_w1  [LL*HDIM*DD];
__device__ __half g_w2  [LL*DD*HDIM];
__device__ __half g_ro  [VV*DD];

// ---------------------------------------------------------------------------
// helpers (base-target PTX only: cp.async, ldmatrix, mma.sync)
// ---------------------------------------------------------------------------
__device__ __forceinline__ uint32_t smem_u32(const void* p) {
    uint32_t a;
    asm("{ .reg .u64 t; cvta.to.shared.u64 t, %1; cvt.u32.u64 %0, t; }"
        : "=r"(a) : "l"(p));
    return a;
}
__device__ __forceinline__ void cp16(uint32_t dst, const void* src) {
    asm volatile("cp.async.cg.shared.global [%0], [%1], 16;" :: "r"(dst), "l"(src));
}
#define CP_COMMIT()  asm volatile("cp.async.commit_group;" ::: "memory")
#define CP_WAIT0()   asm volatile("cp.async.wait_group 0;" ::: "memory")
#define CP_WAIT1()   asm volatile("cp.async.wait_group 1;" ::: "memory")

__device__ __forceinline__ void ldsm4(uint32_t& r0, uint32_t& r1,
                                      uint32_t& r2, uint32_t& r3, uint32_t addr) {
    asm volatile("ldmatrix.sync.aligned.m8n8.x4.shared.b16 {%0,%1,%2,%3}, [%4];"
                 : "=r"(r0), "=r"(r1), "=r"(r2), "=r"(r3) : "r"(addr));
}
__device__ __forceinline__ void ldsm4t(uint32_t& r0, uint32_t& r1,
                                       uint32_t& r2, uint32_t& r3, uint32_t addr) {
    asm volatile("ldmatrix.sync.aligned.m8n8.x4.trans.shared.b16 {%0,%1,%2,%3}, [%4];"
                 : "=r"(r0), "=r"(r1), "=r"(r2), "=r"(r3) : "r"(addr));
}
__device__ __forceinline__ void mma16816(float* d, const uint32_t* a, const uint32_t* b) {
    asm volatile("mma.sync.aligned.m16n8k16.row.col.f32.f16.f16.f32 "
        "{%0,%1,%2,%3}, {%4,%5,%6,%7}, {%8,%9}, {%0,%1,%2,%3};"
        : "+f"(d[0]), "+f"(d[1]), "+f"(d[2]), "+f"(d[3])
        : "r"(a[0]), "r"(a[1]), "r"(a[2]), "r"(a[3]), "r"(b[0]), "r"(b[1]));
}
__device__ __forceinline__ void split2(float v, __half& h, __half& l) {
    h = __float2half(v);
    l = __float2half(v - __half2float(h));
}
__device__ __forceinline__ uint32_t pack2h(__half a, __half b) {
    __half2 hp = __halves2half2(a, b);
    return *(uint32_t*)&hp;
}

// ---------------------------------------------------------------------------
// HMMA GEMM: C[M,N] (+)= A[M,K] * B^T, B stored [N,K] fp16.
// TWOA=1: A = Ah + Al (2-term split). TWOA=0: A = Ah only (readout).
// CTA 128x128, 256 threads = 8 warps as 2(m)x4(n) -> 64x32 warp tiles.
// Register-capped (launch_bounds 256,2 -> 128 regs) so 2 CTAs/SM = 16 warps/SM
// (4/SMSP) to hide LDSM+HMMA latency. KC=32, 3 stages, 90KB smem/CTA.
// grid.x = M-block (fast), grid.y = N-block (slow) -> weight L2 reuse.
// ---------------------------------------------------------------------------
#define STAGES  3
#define KC      32
#define PITCH   80u
#define A_TILE  (128u * PITCH)
#define STAGE_B (3u * A_TILE)
#define SMEM_B  (STAGES * STAGE_B)     // 92160

template<bool BIAS, bool RELU, bool ACCUM, bool SPLIT, bool TWOA>
__global__ __launch_bounds__(256, 2)
void gemm_mma(const __half* __restrict__ Ah, const __half* __restrict__ Al,
              const __half* __restrict__ Bh,
              const float* __restrict__ bias,
              float* __restrict__ C,
              __half* __restrict__ Ch, __half* __restrict__ Cl,
              int M, int N, int K)
{
    extern __shared__ char smem_raw[];
    const uint32_t sb = smem_u32(smem_raw);

    const int tid  = threadIdx.x;
    const int wid  = tid >> 5;
    const int lane = tid & 31;
    const int row0 = blockIdx.x * 128;
    const int col0 = blockIdx.y * 128;
    const int NC   = K / KC;

    // stage loader over 256 threads: A hi/lo 1024 cp16 (4/thr or 2/thr), B 512 (2/thr)
    auto load_stage = [&](int s) {
        const uint32_t stg = sb + (uint32_t)(s % STAGES) * STAGE_B;
        const int k0 = s * KC;
        const int a_iters = TWOA ? 4 : 2;
        #pragma unroll
        for (int i = 0; i < 4; i++) {
            if (i >= a_iters) break;
            int f = i * 256 + tid;            // 0..1023
            int sub = f >> 9;                 // 0:Ah 1:Al
            int rem = f & 511;
            int r = rem >> 2, c = rem & 3;
            const __half* src = ((sub == 0) ? Ah : Al)
                              + (size_t)(row0 + r) * K + k0 + c * 8;
            cp16(stg + (uint32_t)sub * A_TILE + (uint32_t)r * PITCH + c * 16, src);
        }
        #pragma unroll
        for (int i = 0; i < 2; i++) {
            int f = i * 256 + tid;            // 0..511
            int r = f >> 2, c = f & 3;
            const __half* src = Bh + (size_t)(col0 + r) * K + k0 + c * 8;
            cp16(stg + 2u*A_TILE + (uint32_t)r * PITCH + c * 16, src);
        }
        CP_COMMIT();
    };

    load_stage(0);
    if (NC > 1) load_stage(1);

    const int wm = wid >> 2;   // 0..1 -> 64-row block
    const int wn = wid & 3;    // 0..3 -> 32-col block

    float acc[4][4][4];
    #pragma unroll
    for (int a = 0; a < 4; a++)
        #pragma unroll
        for (int b = 0; b < 4; b++)
            #pragma unroll
            for (int c = 0; c < 4; c++) acc[a][b][c] = 0.f;

    for (int i = 0; i < NC; i++) {
        if (i < NC - 1) CP_WAIT1(); else CP_WAIT0();
        __syncthreads();
        if (i + 2 < NC) load_stage(i + 2);

        const uint32_t stg  = sb + (uint32_t)(i % STAGES) * STAGE_B;
        const uint32_t ah_b = stg;
        const uint32_t al_b = stg + A_TILE;
        const uint32_t bh_b = stg + 2u*A_TILE;

        #pragma unroll
        for (int ks = 0; ks < 2; ks++) {
            uint32_t ah[4][4], al[4][4], bf[4][2];
            const uint32_t a_coff = (uint32_t)ks * 32 + ((lane >> 4) << 4);
            #pragma unroll
            for (int mi = 0; mi < 4; mi++) {
                uint32_t r = (uint32_t)(wm * 64 + mi * 16 + (lane & 15));
                ldsm4(ah[mi][0], ah[mi][1], ah[mi][2], ah[mi][3], ah_b + r * PITCH + a_coff);
                if (TWOA)
                    ldsm4(al[mi][0], al[mi][1], al[mi][2], al[mi][3], al_b + r * PITCH + a_coff);
            }
            const uint32_t b_coff = (uint32_t)ks * 32 + (((lane >> 3) & 1) << 4);
            #pragma unroll
            for (int g = 0; g < 2; g++) {
                uint32_t r = (uint32_t)(wn * 32 + g * 16 + (lane & 7) + ((lane >> 4) << 3));
                ldsm4(bf[2*g][0], bf[2*g][1], bf[2*g+1][0], bf[2*g+1][1], bh_b + r * PITCH + b_coff);
            }
            #pragma unroll
            for (int mi = 0; mi < 4; mi++)
                #pragma unroll
                for (int ni = 0; ni < 4; ni++) {
                    mma16816(acc[mi][ni], ah[mi], bf[ni]);
                    if (TWOA) mma16816(acc[mi][ni], al[mi], bf[ni]);
                }
        }
    }

    #pragma unroll
    for (int mi = 0; mi < 4; mi++) {
        #pragma unroll
        for (int rg = 0; rg < 2; rg++) {
            int r = row0 + wm * 64 + mi * 16 + (lane >> 2) + rg * 8;
            #pragma unroll
            for (int ni = 0; ni < 4; ni++) {
                int c = col0 + wn * 32 + ni * 8 + (lane & 3) * 2;
                float v0 = acc[mi][ni][rg * 2 + 0];
                float v1 = acc[mi][ni][rg * 2 + 1];
                if (BIAS)  { v0 += bias[c]; v1 += bias[c + 1]; }
                if (RELU)  { v0 = fmaxf(v0, 0.f); v1 = fmaxf(v1, 0.f); }
                if (ACCUM) {
                    float2 o = *(const float2*)&C[(size_t)r * N + c];
                    v0 += o.x; v1 += o.y;
                }
                if (SPLIT) {
                    __half h0, l0, h1, l1;
                    split2(v0, h0, l0); split2(v1, h1, l1);
                    *(__half2*)&Ch[(size_t)r * N + c] = __halves2half2(h0, h1);
                    *(__half2*)&Cl[(size_t)r * N + c] = __halves2half2(l0, l1);
                } else {
                    *(float2*)&C[(size_t)r * N + c] = make_float2(v0, v1);
                }
            }
        }
    }
}

// ---------------------------------------------------------------------------
// Tensor-core causal flash attention over split-fp16 qkv [M, 3072].
// (unchanged from R8/R9 — ~0.5 ms, not the bottleneck)
// ---------------------------------------------------------------------------
#define AT_PITCH 144u
#define AT_TILE  (64u * AT_PITCH)
#define AT_STAGE (4u * AT_TILE)
#define AT_SMEM  (2u * AT_STAGE)      // 73728

__global__ __launch_bounds__(128, 2)
void attn_mma(const __half* __restrict__ QKVh, const __half* __restrict__ QKVl,
              __half* __restrict__ Yh, __half* __restrict__ Yl)
{
    extern __shared__ char smem_raw[];
    const uint32_t sb = smem_u32(smem_raw);

    const int tid  = threadIdx.x;
    const int wid  = tid >> 5;
    const int lane = tid & 31;
    const int bh = blockIdx.y;
    const int b  = bh >> 4;
    const int h  = bh & 15;
    const int qt = (int)(gridDim.x - 1 - blockIdx.x);
    const int qrow = b * TT + qt * 64;

    auto load_kv = [&](int st, int stile) {
        const uint32_t stg = sb + (uint32_t)st * AT_STAGE;
        const int srow = b * TT + stile * 64;
        #pragma unroll
        for (int i = 0; i < 16; i++) {
            int f = i * 128 + tid;
            int sub = f >> 9;
            int rem = f & 511;
            int r = rem >> 3, c = rem & 7;
            int colbase = ((sub < 2) ? DD : 2*DD) + h * 64;
            const __half* src = ((sub & 1) ? QKVl : QKVh)
                              + (size_t)(srow + r) * QKVD + colbase + c * 8;
            cp16(stg + (uint32_t)sub * AT_TILE + (uint32_t)r * AT_PITCH + c * 16, src);
        }
        CP_COMMIT();
    };

    load_kv(0, 0);
    {
        const uint32_t qstg = sb + AT_STAGE;
        #pragma unroll
        for (int i = 0; i < 8; i++) {
            int f = i * 128 + tid;
            int sub = f >> 9;
            int rem = f & 511;
            int r = rem >> 3, c = rem & 7;
            const __half* src = (sub ? QKVl : QKVh)
                              + (size_t)(qrow + r) * QKVD + h * 64 + c * 8;
            cp16(qstg + (uint32_t)sub * AT_TILE + (uint32_t)r * AT_PITCH + c * 16, src);
        }
        CP_COMMIT();
    }
    CP_WAIT0();
    __syncthreads();

    uint32_t qf_h[4][4], qf_l[4][4];
    {
        const uint32_t qstg = sb + AT_STAGE;
        uint32_t r = (uint32_t)(wid * 16 + (lane & 15));
        #pragma unroll
        for (int ks = 0; ks < 4; ks++) {
            uint32_t coff = (uint32_t)ks * 32 + ((lane >> 4) << 4);
            ldsm4(qf_h[ks][0], qf_h[ks][1], qf_h[ks][2], qf_h[ks][3],
                  qstg + r * AT_PITCH + coff);
            ldsm4(qf_l[ks][0], qf_l[ks][1], qf_l[ks][2], qf_l[ks][3],
                  qstg + AT_TILE + r * AT_PITCH + coff);
        }
    }
    __syncthreads();
    if (qt >= 1) load_kv(1, 1);

    float yacc[8][4];
    #pragma unroll
    for (int i = 0; i < 8; i++)
        #pragma unroll
        for (int j = 0; j < 4; j++) yacc[i][j] = 0.f;
    float m0 = -1e30f, m1 = -1e30f, l0 = 0.f, l1 = 0.f;

    for (int st = 0; st <= qt; st++) {
        if (st < qt) CP_WAIT1(); else CP_WAIT0();
        __syncthreads();
        const uint32_t stg = sb + (uint32_t)(st & 1) * AT_STAGE;

        float sacc[8][4];
        #pragma unroll
        for (int i = 0; i < 8; i++)
            #pragma unroll
            for (int j = 0; j < 4; j++) sacc[i][j] = 0.f;

        const uint32_t kb_h = stg;
        const uint32_t kb_l = stg + AT_TILE;
        #pragma unroll
        for (int ks = 0; ks < 4; ks++) {
            const uint32_t coff = (uint32_t)ks * 32 + (((lane >> 3) & 1) << 4);
            #pragma unroll
            for (int nbp = 0; nbp < 4; nbp++) {
                uint32_t r = (uint32_t)(nbp * 16 + (lane & 7) + ((lane >> 4) << 3));
                uint32_t kh[4], kl[4];
                ldsm4(kh[0], kh[1], kh[2], kh[3], kb_h + r * AT_PITCH + coff);
                mma16816(sacc[2*nbp],   qf_h[ks], kh + 0);
                mma16816(sacc[2*nbp+1], qf_h[ks], kh + 2);
                mma16816(sacc[2*nbp],   qf_l[ks], kh + 0);
                mma16816(sacc[2*nbp+1], qf_l[ks], kh + 2);
                ldsm4(kl[0], kl[1], kl[2], kl[3], kb_l + r * AT_PITCH + coff);
                mma16816(sacc[2*nbp],   qf_h[ks], kl + 0);
                mma16816(sacc[2*nbp+1], qf_h[ks], kl + 2);
            }
        }

        #pragma unroll
        for (int ni = 0; ni < 8; ni++)
            #pragma unroll
            for (int j = 0; j < 4; j++) sacc[ni][j] *= 0.125f;

        if (st == qt) {
            int q0 = wid * 16 + (lane >> 2);
            #pragma unroll
            for (int ni = 0; ni < 8; ni++) {
                int s0c = ni * 8 + 2 * (lane & 3);
                if (s0c     > q0)     sacc[ni][0] = -1e30f;
                if (s0c + 1 > q0)     sacc[ni][1] = -1e30f;
                if (s0c     > q0 + 8) sacc[ni][2] = -1e30f;
                if (s0c + 1 > q0 + 8) sacc[ni][3] = -1e30f;
            }
        }

        float mx0 = -1e30f, mx1 = -1e30f;
        #pragma unroll
        for (int ni = 0; ni < 8; ni++) {
            mx0 = fmaxf(mx0, fmaxf(sacc[ni][0], sacc[ni][1]));
            mx1 = fmaxf(mx1, fmaxf(sacc[ni][2], sacc[ni][3]));
        }
        mx0 = fmaxf(mx0, __shfl_xor_sync(0xffffffffu, mx0, 1));
        mx0 = fmaxf(mx0, __shfl_xor_sync(0xffffffffu, mx0, 2));
        mx1 = fmaxf(mx1, __shfl_xor_sync(0xffffffffu, mx1, 1));
        mx1 = fmaxf(mx1, __shfl_xor_sync(0xffffffffu, mx1, 2));

        float mn0 = fmaxf(m0, mx0), mn1 = fmaxf(m1, mx1);
        float c0 = __expf(m0 - mn0), c1 = __expf(m1 - mn1);
        l0 *= c0; l1 *= c1;
        #pragma unroll
        for (int db = 0; db < 8; db++) {
            yacc[db][0] *= c0; yacc[db][1] *= c0;
            yacc[db][2] *= c1; yacc[db][3] *= c1;
        }

        uint32_t pf_h[4][4], pf_l[4][4];
        float s0 = 0.f, s1 = 0.f;
        #pragma unroll
        for (int ni = 0; ni < 8; ni++) {
            float p0 = __expf(sacc[ni][0] - mn0);
            float p1 = __expf(sacc[ni][1] - mn0);
            float p2 = __expf(sacc[ni][2] - mn1);
            float p3 = __expf(sacc[ni][3] - mn1);
            s0 += p0 + p1; s1 += p2 + p3;
            __half h0, lo0, h1, lo1, h2, lo2, h3, lo3;
            split2(p0, h0, lo0); split2(p1, h1, lo1);
            split2(p2, h2, lo2); split2(p3, h3, lo3);
            int ks = ni >> 1;
            if ((ni & 1) == 0) {
                pf_h[ks][0] = pack2h(h0, h1);  pf_h[ks][1] = pack2h(h2, h3);
                pf_l[ks][0] = pack2h(lo0, lo1); pf_l[ks][1] = pack2h(lo2, lo3);
            } else {
                pf_h[ks][2] = pack2h(h0, h1);  pf_h[ks][3] = pack2h(h2, h3);
                pf_l[ks][2] = pack2h(lo0, lo1); pf_l[ks][3] = pack2h(lo2, lo3);
            }
        }
        s0 += __shfl_xor_sync(0xffffffffu, s0, 1);
        s0 += __shfl_xor_sync(0xffffffffu, s0, 2);
        s1 += __shfl_xor_sync(0xffffffffu, s1, 1);
        s1 += __shfl_xor_sync(0xffffffffu, s1, 2);
        l0 += s0; l1 += s1;
        m0 = mn0; m1 = mn1;

        const uint32_t vb_h = stg + 2u * AT_TILE;
        const uint32_t vb_l = stg + 3u * AT_TILE;
        #pragma unroll
        for (int ks = 0; ks < 4; ks++) {
            #pragma unroll
            for (int dbp = 0; dbp < 4; dbp++) {
                uint32_t raddr = (uint32_t)(ks * 16 + (lane & 15)) * AT_PITCH
                               + (uint32_t)dbp * 32 + ((lane >> 4) << 4);
                uint32_t vh[4], vl[4];
                ldsm4t(vh[0], vh[1], vh[2], vh[3], vb_h + raddr);
                mma16816(yacc[2*dbp],   pf_h[ks], vh + 0);
                mma16816(yacc[2*dbp+1], pf_h[ks], vh + 2);
                mma16816(yacc[2*dbp],   pf_l[ks], vh + 0);
                mma16816(yacc[2*dbp+1], pf_l[ks], vh + 2);
                ldsm4t(vl[0], vl[1], vl[2], vl[3], vb_l + raddr);
                mma16816(yacc[2*dbp],   pf_h[ks], vl + 0);
                mma16816(yacc[2*dbp+1], pf_h[ks], vl + 2);
            }
        }

        if (st + 2 <= qt) {
            __syncthreads();
            load_kv(st & 1, st + 2);
        }
    }

    float inv0 = 1.f / l0, inv1 = 1.f / l1;
    int r0g = qrow + wid * 16 + (lane >> 2);
    size_t base0 = (size_t)r0g * DD + h * 64;
    size_t base1 = base0 + (size_t)8 * DD;
    #pragma unroll
    for (int db = 0; db < 8; db++) {
        int cc = db * 8 + 2 * (lane & 3);
        __half h0, lo0, h1, lo1;
        split2(yacc[db][0] * inv0, h0, lo0);
        split2(yacc[db][1] * inv0, h1, lo1);
        *(__half2*)&Yh[base0 + cc] = __halves2half2(h0, h1);
        *(__half2*)&Yl[base0 + cc] = __halves2half2(lo0, lo1);
        split2(yacc[db][2] * inv1, h0, lo0);
        split2(yacc[db][3] * inv1, h1, lo1);
        *(__half2*)&Yh[base1 + cc] = __halves2half2(h0, h1);
        *(__half2*)&Yl[base1 + cc] = __halves2half2(lo0, lo1);
    }
}

// ---------------------------------------------------------------------------
// Fused embedding + positional encoding + LayerNorm(ln1, layer 0).
// ---------------------------------------------------------------------------
__global__ __launch_bounds__(256) void embed_ln_kernel(const int* __restrict__ tokens,
                                                       const float* __restrict__ emb,
                                                       const float* __restrict__ w,
                                                       const float* __restrict__ b,
                                                       float* __restrict__ x,
                                                       __half* __restrict__ yh,
                                                       __half* __restrict__ yl)
{
    __shared__ float red[8];
    int row = blockIdx.x;
    int tid = threadIdx.x;
    int bb  = row >> 11;
    int t   = row & (TT - 1);
    int tok = (t == 0) ? 0 : tokens[bb * TT + t - 1];

    int c = tid * 4;
    float v[4];
    #pragma unroll
    for (int j = 0; j < 4; j++) {
        int d = c + j;
        int k = d & 1;
        double e = (double)(d - k) / (double)DD;
        float freq = (float)exp(-e * 11.512925464970229);
        float arg = (float)t * freq + 1.5707963267948966f * (float)k;
        v[j] = emb[(size_t)tok * DD + d] + sinf(arg);
    }
    *(float4*)&x[(size_t)row * DD + c] = make_float4(v[0], v[1], v[2], v[3]);

    float s = v[0] + v[1] + v[2] + v[3];
    #pragma unroll
    for (int o = 16; o > 0; o >>= 1) s += __shfl_xor_sync(0xffffffffu, s, o);
    if ((tid & 31) == 0) red[tid >> 5] = s;
    __syncthreads();
    float tot = 0.f;
    #pragma unroll
    for (int i = 0; i < 8; i++) tot += red[i];
    float mean = tot * (1.0f / DD);
    __syncthreads();

    float dx0 = v[0]-mean, dx1 = v[1]-mean, dx2 = v[2]-mean, dx3 = v[3]-mean;
    float s2 = dx0*dx0 + dx1*dx1 + dx2*dx2 + dx3*dx3;
    #pragma unroll
    for (int o = 16; o > 0; o >>= 1) s2 += __shfl_xor_sync(0xffffffffu, s2, o);
    if ((tid & 31) == 0) red[tid >> 5] = s2;
    __syncthreads();
    float tot2 = 0.f;
    #pragma unroll
    for (int i = 0; i < 8; i++) tot2 += red[i];
    float inv = rsqrtf(tot2 * (1.0f / DD) + 1e-5f);

    float4 wv = *(const float4*)&w[c];
    float4 bv = *(const float4*)&b[c];
    float o0 = dx0 * inv * wv.x + bv.x;
    float o1 = dx1 * inv * wv.y + bv.y;
    float o2 = dx2 * inv * wv.z + bv.z;
    float o3 = dx3 * inv * wv.w + bv.w;
    __half h0, l0, h1, l1, h2, l2, h3, l3;
    split2(o0, h0, l0); split2(o1, h1, l1); split2(o2, h2, l2); split2(o3, h3, l3);
    size_t off = (size_t)row * DD + c;
    *(__half2*)&yh[off]     = __halves2half2(h0, h1);
    *(__half2*)&yh[off + 2] = __halves2half2(h2, h3);
    *(__half2*)&yl[off]     = __halves2half2(l0, l1);
    *(__half2*)&yl[off + 2] = __halves2half2(l2, l3);
}

// ---------------------------------------------------------------------------
// LayerNorm -> split fp16 hi/lo output
// ---------------------------------------------------------------------------
__global__ __launch_bounds__(256) void ln_split_kernel(const float* __restrict__ x,
                                                       __half* __restrict__ yh,
                                                       __half* __restrict__ yl,
                                                       const float* __restrict__ w,
                                                       const float* __restrict__ b)
{
    __shared__ float red[8];
    int row = blockIdx.x;
    int tid = threadIdx.x;
    const float* xr = x + (size_t)row * DD;
    float4 xv = *(const float4*)&xr[tid * 4];

    float s = xv.x + xv.y + xv.z + xv.w;
    #pragma unroll
    for (int o = 16; o > 0; o >>= 1) s += __shfl_xor_sync(0xffffffffu, s, o);
    if ((tid & 31) == 0) red[tid >> 5] = s;
    __syncthreads();
    float tot = 0.f;
    #pragma unroll
    for (int i = 0; i < 8; i++) tot += red[i];
    float mean = tot * (1.0f / DD);
    __syncthreads();

    float dx0 = xv.x - mean, dx1 = xv.y - mean, dx2 = xv.z - mean, dx3 = xv.w - mean;
    float s2 = dx0*dx0 + dx1*dx1 + dx2*dx2 + dx3*dx3;
    #pragma unroll
    for (int o = 16; o > 0; o >>= 1) s2 += __shfl_xor_sync(0xffffffffu, s2, o);
    if ((tid & 31) == 0) red[tid >> 5] = s2;
    __syncthreads();
    float tot2 = 0.f;
    #pragma unroll
    for (int i = 0; i < 8; i++) tot2 += red[i];
    float inv = rsqrtf(tot2 * (1.0f / DD) + 1e-5f);

    int c = tid * 4;
    float4 wv = *(const float4*)&w[c];
    float4 bv = *(const float4*)&b[c];
    float o0 = dx0 * inv * wv.x + bv.x;
    float o1 = dx1 * inv * wv.y + bv.y;
    float o2 = dx2 * inv * wv.z + bv.z;
    float o3 = dx3 * inv * wv.w + bv.w;
    __half h0, l0, h1, l1, h2, l2, h3, l3;
    split2(o0, h0, l0); split2(o1, h1, l1); split2(o2, h2, l2); split2(o3, h3, l3);
    size_t off = (size_t)row * DD + c;
    *(__half2*)&yh[off]     = __halves2half2(h0, h1);
    *(__half2*)&yh[off + 2] = __halves2half2(h2, h3);
    *(__half2*)&yl[off]     = __halves2half2(l0, l1);
    *(__half2*)&yl[off + 2] = __halves2half2(l2, l3);
}

// ---------------------------------------------------------------------------
// Weight conversion kernels (single fp16, vectorized x4)
// ---------------------------------------------------------------------------
__global__ void conv_kernel(const float* __restrict__ s,
                            __half* __restrict__ h, int n4)
{
    int i = blockIdx.x * blockDim.x + threadIdx.x;
    if (i >= n4) return;
    float4 v = *(const float4*)&s[i * 4];
    *(__half2*)&h[i*4]   = __halves2half2(__float2half(v.x), __float2half(v.y));
    *(__half2*)&h[i*4+2] = __halves2half2(__float2half(v.z), __float2half(v.w));
}

__global__ void pack_qkv_kernel(const float* __restrict__ wq,
                                const float* __restrict__ wk,
                                const float* __restrict__ wv,
                                __half* __restrict__ h)
{
    int i = blockIdx.x * blockDim.x + threadIdx.x;
    const int per_layer4 = QKVD * DD / 4;
    if (i >= LL * per_layer4) return;
    int lyr = i / per_layer4;
    int rem = i - lyr * per_layer4;
    int row = rem >> 8;
    int c4  = rem & 255;
    int which = row >> 10;
    int srow  = row & 1023;
    const float* src = (which == 0) ? wq : ((which == 1) ? wk : wv);
    float4 v = *(const float4*)&src[(size_t)lyr * (DD*DD) + (size_t)srow * DD + c4 * 4];
    size_t o = (size_t)i * 4;
    *(__half2*)&h[o]   = __halves2half2(__float2half(v.x), __float2half(v.y));
    *(__half2*)&h[o+2] = __halves2half2(__float2half(v.z), __float2half(v.w));
}

__global__ void transpose_wo_kernel(const float* __restrict__ wo,
                                    __half* __restrict__ h)
{
    int i = blockIdx.x * blockDim.x + threadIdx.x;
    if (i >= LL * DD * DD) return;
    int lyr = i >> 20;
    int rem = i & ((1 << 20) - 1);
    int nrow = rem >> 10;
    int kcol = rem & 1023;
    h[i] = __float2half(wo[((size_t)lyr << 20) + ((size_t)kcol << 10) + nrow]);
}

// ---------------------------------------------------------------------------
// Launch
// ---------------------------------------------------------------------------
extern "C" void kernel_launch(void* const* d_in, const int* in_sizes, int n_in,
                              void* d_out, int out_size)
{
    const int*   tokens = (const int*)  d_in[0];
    const float* emb    = (const float*)d_in[1];
    const float* ln1_w  = (const float*)d_in[2];
    const float* ln1_b  = (const float*)d_in[3];
    const float* w_q    = (const float*)d_in[4];
    const float* w_k    = (const float*)d_in[5];
    const float* w_v    = (const float*)d_in[6];
    const float* w_o    = (const float*)d_in[7];
    const float* ln2_w  = (const float*)d_in[8];
    const float* ln2_b  = (const float*)d_in[9];
    const float* w1     = (const float*)d_in[10];
    const float* b1     = (const float*)d_in[11];
    const float* w2     = (const float*)d_in[12];
    const float* b2     = (const float*)d_in[13];
    const float* ro_w   = (const float*)d_in[14];
    const float* ro_b   = (const float*)d_in[15];
    float* out = (float*)d_out;

    float *x;
    __half *qkvh, *qkvl, *xnh, *xnl, *yh, *yl, *hh, *hl, *xh, *xl;
    __half *wqkv, *wo, *w1w, *w2w, *ro;
    cudaGetSymbolAddress((void**)&x,    g_x);
    cudaGetSymbolAddress((void**)&qkvh, g_qkvh); cudaGetSymbolAddress((void**)&qkvl, g_qkvl);
    cudaGetSymbolAddress((void**)&xnh,  g_xnh);  cudaGetSymbolAddress((void**)&xnl, g_xnl);
    cudaGetSymbolAddress((void**)&yh,   g_yh);   cudaGetSymbolAddress((void**)&yl,  g_yl);
    cudaGetSymbolAddress((void**)&hh,   g_hh);   cudaGetSymbolAddress((void**)&hl,  g_hl);
    cudaGetSymbolAddress((void**)&xh,   g_xh);   cudaGetSymbolAddress((void**)&xl,  g_xl);
    cudaGetSymbolAddress((void**)&wqkv, g_wqkv);
    cudaGetSymbolAddress((void**)&wo,   g_wo);
    cudaGetSymbolAddress((void**)&w1w,  g_w1);
    cudaGetSymbolAddress((void**)&w2w,  g_w2);
    cudaGetSymbolAddress((void**)&ro,   g_ro);

    cudaFuncSetAttribute((const void*)gemm_mma<false,false,false,true,true>,
                         cudaFuncAttributeMaxDynamicSharedMemorySize, SMEM_B);
    cudaFuncSetAttribute((const void*)gemm_mma<false,false,true,false,true>,
                         cudaFuncAttributeMaxDynamicSharedMemorySize, SMEM_B);
    cudaFuncSetAttribute((const void*)gemm_mma<true,true,false,true,true>,
                         cudaFuncAttributeMaxDynamicSharedMemorySize, SMEM_B);
    cudaFuncSetAttribute((const void*)gemm_mma<true,false,true,false,true>,
                         cudaFuncAttributeMaxDynamicSharedMemorySize, SMEM_B);
    cudaFuncSetAttribute((const void*)gemm_mma<true,false,true,true,true>,
                         cudaFuncAttributeMaxDynamicSharedMemorySize, SMEM_B);
    cudaFuncSetAttribute((const void*)gemm_mma<true,false,false,false,false>,
                         cudaFuncAttributeMaxDynamicSharedMemorySize, SMEM_B);
    cudaFuncSetAttribute((const void*)attn_mma,
                         cudaFuncAttributeMaxDynamicSharedMemorySize, AT_SMEM);

    // grid: x = M-block (fast), y = N-block (slow)
    const dim3 gQKV(MM/128, QKVD/128);    // 32 x 24
    const dim3 gD  (MM/128, DD/128);      // 32 x 8
    const dim3 gH  (MM/128, HDIM/128);    // 32 x 32
    const dim3 gV  (MM/128, VV/128);      // 32 x 250
    const dim3 gA  (TT/64, BB*HH);        // 32 x 32

    pack_qkv_kernel<<<(LL*QKVD*DD/4 + 255)/256, 256>>>(w_q, w_k, w_v, wqkv);
    embed_ln_kernel<<<MM, 256>>>(tokens, emb, ln1_w, ln1_b, x, xnh, xnl);
    transpose_wo_kernel<<<(LL*DD*DD + 255)/256, 256>>>(w_o, wo);
    gemm_mma<false,false,false,true,true><<<gQKV, 256, SMEM_B>>>(
        xnh, xnl, wqkv, nullptr, nullptr, qkvh, qkvl, MM, QKVD, DD);
    conv_kernel<<<(LL*HDIM*DD/4 + 255)/256, 256>>>(w1, w1w, LL*HDIM*DD/4);
    conv_kernel<<<(LL*DD*HDIM/4 + 255)/256, 256>>>(w2, w2w, LL*DD*HDIM/4);
    conv_kernel<<<(VV*DD/4 + 255)/256, 256>>>(ro_w, ro, VV*DD/4);

    for (int l = 0; l < LL; l++) {
        const __half* wqkv_l = wqkv + (size_t)l * QKVD * DD;
        const __half* wo_l   = wo   + (size_t)l * DD * DD;
        const __half* w1_l   = w1w  + (size_t)l * HDIM * DD;
        const __half* w2_l   = w2w  + (size_t)l * DD * HDIM;

        if (l > 0) {
            ln_split_kernel<<<MM, 256>>>(x, xnh, xnl, ln1_w + (size_t)l*DD, ln1_b + (size_t)l*DD);
            gemm_mma<false,false,false,true,true><<<gQKV, 256, SMEM_B>>>(
                xnh, xnl, wqkv_l, nullptr, nullptr, qkvh, qkvl, MM, QKVD, DD);
        }

        attn_mma<<<gA, 128, AT_SMEM>>>(qkvh, qkvl, yh, yl);

        gemm_mma<false,false,true,false,true><<<gD, 256, SMEM_B>>>(
            yh, yl, wo_l, nullptr, x, nullptr, nullptr, MM, DD, DD);

        ln_split_kernel<<<MM, 256>>>(x, xnh, xnl, ln2_w + (size_t)l*DD, ln2_b + (size_t)l*DD);

        gemm_mma<true,true,false,true,true><<<gH, 256, SMEM_B>>>(
            xnh, xnl, w1_l, b1 + (size_t)l*HDIM, nullptr, hh, hl, MM, HDIM, DD);

        if (l < LL - 1) {
            gemm_mma<true,false,true,false,true><<<gD, 256, SMEM_B>>>(
                hh, hl, w2_l, b2 + (size_t)l*DD, x, nullptr, nullptr, MM, DD, HDIM);
        } else {
            gemm_mma<true,false,true,true,true><<<gD, 256, SMEM_B>>>(
                hh, hl, w2_l, b2 + (size_t)l*DD, x, xh, xl, MM, DD, HDIM);
        }
    }

    // readout: out = x @ ro_w^T + ro_b — single-term A (error not amplified)
    gemm_mma<true,false,false,false,false><<<gV, 256, SMEM_B>>>(
        xh, xl, ro, ro_b, out, nullptr, nullptr, MM, VV, DD);
}

// round 11
// speedup vs baseline: 1.1465x; 1.1465x over previous
#include <cuda_runtime.h>
#include <cuda_fp16.h>
#include <math.h>
#include <stdint.h>

// ---------------------------------------------------------------------------
// Problem constants
// ---------------------------------------------------------------------------
#define BB   2
#define TT   2048
#define DD   1024
#define HH   16
#define HDIM 4096
#define VV   32000
#define LL   4
#define MM   (BB*TT)      // 4096 rows
#define QKVD (3*DD)       // 3072

// ---------------------------------------------------------------------------
// Static device scratch (no allocations allowed)
// ---------------------------------------------------------------------------
__device__ float g_x  [MM*DD];
__device__ __half g_qkvh[MM*QKVD], g_qkvl[MM*QKVD];
__device__ __half g_xnh[MM*DD],  g_xnl[MM*DD];
__device__ __half g_yh [MM*DD],  g_yl [MM*DD];
__device__ __half g_hh [MM*HDIM];
__device__ __half g_xh [MM*DD];
// single-term fp16 weights (recomputed every launch — weights are inputs)
__device__ __half g_wqkv[LL*QKVD*DD];
__device__ __half g_wo  [LL*DD*DD];
__device__ __half g_w1  [LL*HDIM*DD];
__device__ __half g_w2  [LL*DD*HDIM];
__device__ __half g_ro  [VV*DD];

// ---------------------------------------------------------------------------
// helpers (base-target PTX only: cp.async, ldmatrix, mma.sync)
// ---------------------------------------------------------------------------
__device__ __forceinline__ uint32_t smem_u32(const void* p) {
    uint32_t a;
    asm("{ .reg .u64 t; cvta.to.shared.u64 t, %1; cvt.u32.u64 %0, t; }"
        : "=r"(a) : "l"(p));
    return a;
}
__device__ __forceinline__ void cp16(uint32_t dst, const void* src) {
    asm volatile("cp.async.cg.shared.global [%0], [%1], 16;" :: "r"(dst), "l"(src));
}
#define CP_COMMIT()  asm volatile("cp.async.commit_group;" ::: "memory")
#define CP_WAIT0()   asm volatile("cp.async.wait_group 0;" ::: "memory")
#define CP_WAIT1()   asm volatile("cp.async.wait_group 1;" ::: "memory")

__device__ __forceinline__ void ldsm4(uint32_t& r0, uint32_t& r1,
                                      uint32_t& r2, uint32_t& r3, uint32_t addr) {
    asm volatile("ldmatrix.sync.aligned.m8n8.x4.shared.b16 {%0,%1,%2,%3}, [%4];"
                 : "=r"(r0), "=r"(r1), "=r"(r2), "=r"(r3) : "r"(addr));
}
__device__ __forceinline__ void ldsm4t(uint32_t& r0, uint32_t& r1,
                                       uint32_t& r2, uint32_t& r3, uint32_t addr) {
    asm volatile("ldmatrix.sync.aligned.m8n8.x4.trans.shared.b16 {%0,%1,%2,%3}, [%4];"
                 : "=r"(r0), "=r"(r1), "=r"(r2), "=r"(r3) : "r"(addr));
}
__device__ __forceinline__ void mma16816(float* d, const uint32_t* a, const uint32_t* b) {
    asm volatile("mma.sync.aligned.m16n8k16.row.col.f32.f16.f16.f32 "
        "{%0,%1,%2,%3}, {%4,%5,%6,%7}, {%8,%9}, {%0,%1,%2,%3};"
        : "+f"(d[0]), "+f"(d[1]), "+f"(d[2]), "+f"(d[3])
        : "r"(a[0]), "r"(a[1]), "r"(a[2]), "r"(a[3]), "r"(b[0]), "r"(b[1]));
}
__device__ __forceinline__ void split2(float v, __half& h, __half& l) {
    h = __float2half(v);
    l = __float2half(v - __half2float(h));
}
__device__ __forceinline__ uint32_t pack2h(__half a, __half b) {
    __half2 hp = __halves2half2(a, b);
    return *(uint32_t*)&hp;
}

// ---------------------------------------------------------------------------
// HMMA GEMM: C[M,N] (+)= A[M,K] * B^T, B stored [N,K] fp16.
// TWOA=1: A = Ah + Al (2-term split). TWOA=0: A = Ah only.
// SPLIT: write fp16-hi output Ch; SPLITLO additionally writes Cl.
// CTA 128x128, 128 threads (4 warps 2x2, 64x64 tiles), KC=32, 3 stages,
// 90KB smem -> 2 CTAs/SM.  (R9 config — best measured; mma.sync rate cap.)
// grid.x = M-block (fast), grid.y = N-block (slow) -> weight L2 reuse.
// ---------------------------------------------------------------------------
#define STAGES  3
#define KC      32
#define PITCH   80u
#define A_TILE  (128u * PITCH)
#define STAGE_B (3u * A_TILE)
#define SMEM_B  (STAGES * STAGE_B)     // 92160

template<bool BIAS, bool RELU, bool ACCUM, bool SPLIT, bool SPLITLO, bool TWOA>
__global__ __launch_bounds__(128, 2)
void gemm_mma(const __half* __restrict__ Ah, const __half* __restrict__ Al,
              const __half* __restrict__ Bh,
              const float* __restrict__ bias,
              float* __restrict__ C,
              __half* __restrict__ Ch, __half* __restrict__ Cl,
              int M, int N, int K)
{
    extern __shared__ char smem_raw[];
    const uint32_t sb = smem_u32(smem_raw);

    const int tid  = threadIdx.x;
    const int wid  = tid >> 5;
    const int lane = tid & 31;
    const int row0 = blockIdx.x * 128;
    const int col0 = blockIdx.y * 128;
    const int NC   = K / KC;

    auto load_stage = [&](int s) {
        const uint32_t stg = sb + (uint32_t)(s % STAGES) * STAGE_B;
        const int k0 = s * KC;
        const int a_iters = TWOA ? 8 : 4;
        #pragma unroll
        for (int i = 0; i < 8; i++) {
            if (i >= a_iters) break;
            int f = i * 128 + tid;
            int sub = f >> 9;                 // 0:Ah 1:Al
            int rem = f & 511;
            int r = rem >> 2, c = rem & 3;
            const __half* src = ((sub == 0) ? Ah : Al)
                              + (size_t)(row0 + r) * K + k0 + c * 8;
            cp16(stg + (uint32_t)sub * A_TILE + (uint32_t)r * PITCH + c * 16, src);
        }
        #pragma unroll
        for (int i = 0; i < 4; i++) {
            int f = i * 128 + tid;
            int r = f >> 2, c = f & 3;
            const __half* src = Bh + (size_t)(col0 + r) * K + k0 + c * 8;
            cp16(stg + 2u*A_TILE + (uint32_t)r * PITCH + c * 16, src);
        }
        CP_COMMIT();
    };

    load_stage(0);
    if (NC > 1) load_stage(1);

    const int wm = wid >> 1;
    const int wn = wid & 1;

    float acc[4][8][4];
    #pragma unroll
    for (int a = 0; a < 4; a++)
        #pragma unroll
        for (int b = 0; b < 8; b++)
            #pragma unroll
            for (int c = 0; c < 4; c++) acc[a][b][c] = 0.f;

    for (int i = 0; i < NC; i++) {
        if (i < NC - 1) CP_WAIT1(); else CP_WAIT0();
        __syncthreads();
        if (i + 2 < NC) load_stage(i + 2);

        const uint32_t stg  = sb + (uint32_t)(i % STAGES) * STAGE_B;
        const uint32_t ah_b = stg;
        const uint32_t al_b = stg + A_TILE;
        const uint32_t bh_b = stg + 2u*A_TILE;

        #pragma unroll
        for (int ks = 0; ks < 2; ks++) {
            uint32_t ah[4][4], al[4][4], bf[8][2];
            const uint32_t a_coff = (uint32_t)ks * 32 + ((lane >> 4) << 4);
            #pragma unroll
            for (int mi = 0; mi < 4; mi++) {
                uint32_t r = (uint32_t)(wm * 64 + mi * 16 + (lane & 15));
                ldsm4(ah[mi][0], ah[mi][1], ah[mi][2], ah[mi][3], ah_b + r * PITCH + a_coff);
                if (TWOA)
                    ldsm4(al[mi][0], al[mi][1], al[mi][2], al[mi][3], al_b + r * PITCH + a_coff);
            }
            const uint32_t b_coff = (uint32_t)ks * 32 + (((lane >> 3) & 1) << 4);
            #pragma unroll
            for (int g = 0; g < 4; g++) {
                uint32_t r = (uint32_t)(wn * 64 + g * 16 + (lane & 7) + ((lane >> 4) << 3));
                ldsm4(bf[2*g][0], bf[2*g][1], bf[2*g+1][0], bf[2*g+1][1], bh_b + r * PITCH + b_coff);
            }
            #pragma unroll
            for (int mi = 0; mi < 4; mi++)
                #pragma unroll
                for (int ni = 0; ni < 8; ni++) {
                    mma16816(acc[mi][ni], ah[mi], bf[ni]);
                    if (TWOA) mma16816(acc[mi][ni], al[mi], bf[ni]);
                }
        }
    }

    #pragma unroll
    for (int mi = 0; mi < 4; mi++) {
        #pragma unroll
        for (int rg = 0; rg < 2; rg++) {
            int r = row0 + wm * 64 + mi * 16 + (lane >> 2) + rg * 8;
            #pragma unroll
            for (int ni = 0; ni < 8; ni++) {
                int c = col0 + wn * 64 + ni * 8 + (lane & 3) * 2;
                float v0 = acc[mi][ni][rg * 2 + 0];
                float v1 = acc[mi][ni][rg * 2 + 1];
                if (BIAS)  { v0 += bias[c]; v1 += bias[c + 1]; }
                if (RELU)  { v0 = fmaxf(v0, 0.f); v1 = fmaxf(v1, 0.f); }
                if (ACCUM) {
                    float2 o = *(const float2*)&C[(size_t)r * N + c];
                    v0 += o.x; v1 += o.y;
                }
                if (SPLIT) {
                    __half h0, l0, h1, l1;
                    split2(v0, h0, l0); split2(v1, h1, l1);
                    *(__half2*)&Ch[(size_t)r * N + c] = __halves2half2(h0, h1);
                    if (SPLITLO)
                        *(__half2*)&Cl[(size_t)r * N + c] = __halves2half2(l0, l1);
                } else {
                    *(float2*)&C[(size_t)r * N + c] = make_float2(v0, v1);
                }
            }
        }
    }
}

// ---------------------------------------------------------------------------
// Tensor-core causal flash attention over split-fp16 qkv [M, 3072].
// ---------------------------------------------------------------------------
#define AT_PITCH 144u
#define AT_TILE  (64u * AT_PITCH)
#define AT_STAGE (4u * AT_TILE)
#define AT_SMEM  (2u * AT_STAGE)      // 73728

__global__ __launch_bounds__(128, 2)
void attn_mma(const __half* __restrict__ QKVh, const __half* __restrict__ QKVl,
              __half* __restrict__ Yh, __half* __restrict__ Yl)
{
    extern __shared__ char smem_raw[];
    const uint32_t sb = smem_u32(smem_raw);

    const int tid  = threadIdx.x;
    const int wid  = tid >> 5;
    const int lane = tid & 31;
    const int bh = blockIdx.y;
    const int b  = bh >> 4;
    const int h  = bh & 15;
    const int qt = (int)(gridDim.x - 1 - blockIdx.x);
    const int qrow = b * TT + qt * 64;

    auto load_kv = [&](int st, int stile) {
        const uint32_t stg = sb + (uint32_t)st * AT_STAGE;
        const int srow = b * TT + stile * 64;
        #pragma unroll
        for (int i = 0; i < 16; i++) {
            int f = i * 128 + tid;
            int sub = f >> 9;
            int rem = f & 511;
            int r = rem >> 3, c = rem & 7;
            int colbase = ((sub < 2) ? DD : 2*DD) + h * 64;
            const __half* src = ((sub & 1) ? QKVl : QKVh)
                              + (size_t)(srow + r) * QKVD + colbase + c * 8;
            cp16(stg + (uint32_t)sub * AT_TILE + (uint32_t)r * AT_PITCH + c * 16, src);
        }
        CP_COMMIT();
    };

    load_kv(0, 0);
    {
        const uint32_t qstg = sb + AT_STAGE;
        #pragma unroll
        for (int i = 0; i < 8; i++) {
            int f = i * 128 + tid;
            int sub = f >> 9;
            int rem = f & 511;
            int r = rem >> 3, c = rem & 7;
            const __half* src = (sub ? QKVl : QKVh)
                              + (size_t)(qrow + r) * QKVD + h * 64 + c * 8;
            cp16(qstg + (uint32_t)sub * AT_TILE + (uint32_t)r * AT_PITCH + c * 16, src);
        }
        CP_COMMIT();
    }
    CP_WAIT0();
    __syncthreads();

    uint32_t qf_h[4][4], qf_l[4][4];
    {
        const uint32_t qstg = sb + AT_STAGE;
        uint32_t r = (uint32_t)(wid * 16 + (lane & 15));
        #pragma unroll
        for (int ks = 0; ks < 4; ks++) {
            uint32_t coff = (uint32_t)ks * 32 + ((lane >> 4) << 4);
            ldsm4(qf_h[ks][0], qf_h[ks][1], qf_h[ks][2], qf_h[ks][3],
                  qstg + r * AT_PITCH + coff);
            ldsm4(qf_l[ks][0], qf_l[ks][1], qf_l[ks][2], qf_l[ks][3],
                  qstg + AT_TILE + r * AT_PITCH + coff);
        }
    }
    __syncthreads();
    if (qt >= 1) load_kv(1, 1);

    float yacc[8][4];
    #pragma unroll
    for (int i = 0; i < 8; i++)
        #pragma unroll
        for (int j = 0; j < 4; j++) yacc[i][j] = 0.f;
    float m0 = -1e30f, m1 = -1e30f, l0 = 0.f, l1 = 0.f;

    for (int st = 0; st <= qt; st++) {
        if (st < qt) CP_WAIT1(); else CP_WAIT0();
        __syncthreads();
        const uint32_t stg = sb + (uint32_t)(st & 1) * AT_STAGE;

        float sacc[8][4];
        #pragma unroll
        for (int i = 0; i < 8; i++)
            #pragma unroll
            for (int j = 0; j < 4; j++) sacc[i][j] = 0.f;

        const uint32_t kb_h = stg;
        const uint32_t kb_l = stg + AT_TILE;
        #pragma unroll
        for (int ks = 0; ks < 4; ks++) {
            const uint32_t coff = (uint32_t)ks * 32 + (((lane >> 3) & 1) << 4);
            #pragma unroll
            for (int nbp = 0; nbp < 4; nbp++) {
                uint32_t r = (uint32_t)(nbp * 16 + (lane & 7) + ((lane >> 4) << 3));
                uint32_t kh[4], kl[4];
                ldsm4(kh[0], kh[1], kh[2], kh[3], kb_h + r * AT_PITCH + coff);
                mma16816(sacc[2*nbp],   qf_h[ks], kh + 0);
                mma16816(sacc[2*nbp+1], qf_h[ks], kh + 2);
                mma16816(sacc[2*nbp],   qf_l[ks], kh + 0);
                mma16816(sacc[2*nbp+1], qf_l[ks], kh + 2);
                ldsm4(kl[0], kl[1], kl[2], kl[3], kb_l + r * AT_PITCH + coff);
                mma16816(sacc[2*nbp],   qf_h[ks], kl + 0);
                mma16816(sacc[2*nbp+1], qf_h[ks], kl + 2);
            }
        }

        #pragma unroll
        for (int ni = 0; ni < 8; ni++)
            #pragma unroll
            for (int j = 0; j < 4; j++) sacc[ni][j] *= 0.125f;

        if (st == qt) {
            int q0 = wid * 16 + (lane >> 2);
            #pragma unroll
            for (int ni = 0; ni < 8; ni++) {
                int s0c = ni * 8 + 2 * (lane & 3);
                if (s0c     > q0)     sacc[ni][0] = -1e30f;
                if (s0c + 1 > q0)     sacc[ni][1] = -1e30f;
                if (s0c     > q0 + 8) sacc[ni][2] = -1e30f;
                if (s0c + 1 > q0 + 8) sacc[ni][3] = -1e30f;
            }
        }

        float mx0 = -1e30f, mx1 = -1e30f;
        #pragma unroll
        for (int ni = 0; ni < 8; ni++) {
            mx0 = fmaxf(mx0, fmaxf(sacc[ni][0], sacc[ni][1]));
            mx1 = fmaxf(mx1, fmaxf(sacc[ni][2], sacc[ni][3]));
        }
        mx0 = fmaxf(mx0, __shfl_xor_sync(0xffffffffu, mx0, 1));
        mx0 = fmaxf(mx0, __shfl_xor_sync(0xffffffffu, mx0, 2));
        mx1 = fmaxf(mx1, __shfl_xor_sync(0xffffffffu, mx1, 1));
        mx1 = fmaxf(mx1, __shfl_xor_sync(0xffffffffu, mx1, 2));

        float mn0 = fmaxf(m0, mx0), mn1 = fmaxf(m1, mx1);
        float c0 = __expf(m0 - mn0), c1 = __expf(m1 - mn1);
        l0 *= c0; l1 *= c1;
        #pragma unroll
        for (int db = 0; db < 8; db++) {
            yacc[db][0] *= c0; yacc[db][1] *= c0;
            yacc[db][2] *= c1; yacc[db][3] *= c1;
        }

        uint32_t pf_h[4][4], pf_l[4][4];
        float s0 = 0.f, s1 = 0.f;
        #pragma unroll
        for (int ni = 0; ni < 8; ni++) {
            float p0 = __expf(sacc[ni][0] - mn0);
            float p1 = __expf(sacc[ni][1] - mn0);
            float p2 = __expf(sacc[ni][2] - mn1);
            float p3 = __expf(sacc[ni][3] - mn1);
            s0 += p0 + p1; s1 += p2 + p3;
            __half h0, lo0, h1, lo1, h2, lo2, h3, lo3;
            split2(p0, h0, lo0); split2(p1, h1, lo1);
            split2(p2, h2, lo2); split2(p3, h3, lo3);
            int ks = ni >> 1;
            if ((ni & 1) == 0) {
                pf_h[ks][0] = pack2h(h0, h1);  pf_h[ks][1] = pack2h(h2, h3);
                pf_l[ks][0] = pack2h(lo0, lo1); pf_l[ks][1] = pack2h(lo2, lo3);
            } else {
                pf_h[ks][2] = pack2h(h0, h1);  pf_h[ks][3] = pack2h(h2, h3);
                pf_l[ks][2] = pack2h(lo0, lo1); pf_l[ks][3] = pack2h(lo2, lo3);
            }
        }
        s0 += __shfl_xor_sync(0xffffffffu, s0, 1);
        s0 += __shfl_xor_sync(0xffffffffu, s0, 2);
        s1 += __shfl_xor_sync(0xffffffffu, s1, 1);
        s1 += __shfl_xor_sync(0xffffffffu, s1, 2);
        l0 += s0; l1 += s1;
        m0 = mn0; m1 = mn1;

        const uint32_t vb_h = stg + 2u * AT_TILE;
        const uint32_t vb_l = stg + 3u * AT_TILE;
        #pragma unroll
        for (int ks = 0; ks < 4; ks++) {
            #pragma unroll
            for (int dbp = 0; dbp < 4; dbp++) {
                uint32_t raddr = (uint32_t)(ks * 16 + (lane & 15)) * AT_PITCH
                               + (uint32_t)dbp * 32 + ((lane >> 4) << 4);
                uint32_t vh[4], vl[4];
                ldsm4t(vh[0], vh[1], vh[2], vh[3], vb_h + raddr);
                mma16816(yacc[2*dbp],   pf_h[ks], vh + 0);
                mma16816(yacc[2*dbp+1], pf_h[ks], vh + 2);
                mma16816(yacc[2*dbp],   pf_l[ks], vh + 0);
                mma16816(yacc[2*dbp+1], pf_l[ks], vh + 2);
                ldsm4t(vl[0], vl[1], vl[2], vl[3], vb_l + raddr);
                mma16816(yacc[2*dbp],   pf_h[ks], vl + 0);
                mma16816(yacc[2*dbp+1], pf_h[ks], vl + 2);
            }
        }

        if (st + 2 <= qt) {
            __syncthreads();
            load_kv(st & 1, st + 2);
        }
    }

    float inv0 = 1.f / l0, inv1 = 1.f / l1;
    int r0g = qrow + wid * 16 + (lane >> 2);
    size_t base0 = (size_t)r0g * DD + h * 64;
    size_t base1 = base0 + (size_t)8 * DD;
    #pragma unroll
    for (int db = 0; db < 8; db++) {
        int cc = db * 8 + 2 * (lane & 3);
        __half h0, lo0, h1, lo1;
        split2(yacc[db][0] * inv0, h0, lo0);
        split2(yacc[db][1] * inv0, h1, lo1);
        *(__half2*)&Yh[base0 + cc] = __halves2half2(h0, h1);
        *(__half2*)&Yl[base0 + cc] = __halves2half2(lo0, lo1);
        split2(yacc[db][2] * inv1, h0, lo0);
        split2(yacc[db][3] * inv1, h1, lo1);
        *(__half2*)&Yh[base1 + cc] = __halves2half2(h0, h1);
        *(__half2*)&Yl[base1 + cc] = __halves2half2(lo0, lo1);
    }
}

// ---------------------------------------------------------------------------
// Fused embedding + positional encoding + LayerNorm(ln1, layer 0).
// ---------------------------------------------------------------------------
__global__ __launch_bounds__(256) void embed_ln_kernel(const int* __restrict__ tokens,
                                                       const float* __restrict__ emb,
                                                       const float* __restrict__ w,
                                                       const float* __restrict__ b,
                                                       float* __restrict__ x,
                                                       __half* __restrict__ yh,
                                                       __half* __restrict__ yl)
{
    __shared__ float red[8];
    int row = blockIdx.x;
    int tid = threadIdx.x;
    int bb  = row >> 11;
    int t   = row & (TT - 1);
    int tok = (t == 0) ? 0 : tokens[bb * TT + t - 1];

    int c = tid * 4;
    float v[4];
    #pragma unroll
    for (int j = 0; j < 4; j++) {
        int d = c + j;
        int k = d & 1;
        double e = (double)(d - k) / (double)DD;
        float freq = (float)exp(-e * 11.512925464970229);
        float arg = (float)t * freq + 1.5707963267948966f * (float)k;
        v[j] = emb[(size_t)tok * DD + d] + sinf(arg);
    }
    *(float4*)&x[(size_t)row * DD + c] = make_float4(v[0], v[1], v[2], v[3]);

    float s = v[0] + v[1] + v[2] + v[3];
    #pragma unroll
    for (int o = 16; o > 0; o >>= 1) s += __shfl_xor_sync(0xffffffffu, s, o);
    if ((tid & 31) == 0) red[tid >> 5] = s;
    __syncthreads();
    float tot = 0.f;
    #pragma unroll
    for (int i = 0; i < 8; i++) tot += red[i];
    float mean = tot * (1.0f / DD);
    __syncthreads();

    float dx0 = v[0]-mean, dx1 = v[1]-mean, dx2 = v[2]-mean, dx3 = v[3]-mean;
    float s2 = dx0*dx0 + dx1*dx1 + dx2*dx2 + dx3*dx3;
    #pragma unroll
    for (int o = 16; o > 0; o >>= 1) s2 += __shfl_xor_sync(0xffffffffu, s2, o);
    if ((tid & 31) == 0) red[tid >> 5] = s2;
    __syncthreads();
    float tot2 = 0.f;
    #pragma unroll
    for (int i = 0; i < 8; i++) tot2 += red[i];
    float inv = rsqrtf(tot2 * (1.0f / DD) + 1e-5f);

    float4 wv = *(const float4*)&w[c];
    float4 bv = *(const float4*)&b[c];
    float o0 = dx0 * inv * wv.x + bv.x;
    float o1 = dx1 * inv * wv.y + bv.y;
    float o2 = dx2 * inv * wv.z + bv.z;
    float o3 = dx3 * inv * wv.w + bv.w;
    __half h0, l0, h1, l1, h2, l2, h3, l3;
    split2(o0, h0, l0); split2(o1, h1, l1); split2(o2, h2, l2); split2(o3, h3, l3);
    size_t off = (size_t)row * DD + c;
    *(__half2*)&yh[off]     = __halves2half2(h0, h1);
    *(__half2*)&yh[off + 2] = __halves2half2(h2, h3);
    *(__half2*)&yl[off]     = __halves2half2(l0, l1);
    *(__half2*)&yl[off + 2] = __halves2half2(l2, l3);
}

// ---------------------------------------------------------------------------
// LayerNorm -> split fp16 hi/lo output
// ---------------------------------------------------------------------------
__global__ __launch_bounds__(256) void ln_split_kernel(const float* __restrict__ x,
                                                       __half* __restrict__ yh,
                                                       __half* __restrict__ yl,
                                                       const float* __restrict__ w,
                                                       const float* __restrict__ b)
{
    __shared__ float red[8];
    int row = blockIdx.x;
    int tid = threadIdx.x;
    const float* xr = x + (size_t)row * DD;
    float4 xv = *(const float4*)&xr[tid * 4];

    float s = xv.x + xv.y + xv.z + xv.w;
    #pragma unroll
    for (int o = 16; o > 0; o >>= 1) s += __shfl_xor_sync(0xffffffffu, s, o);
    if ((tid & 31) == 0) red[tid >> 5] = s;
    __syncthreads();
    float tot = 0.f;
    #pragma unroll
    for (int i = 0; i < 8; i++) tot += red[i];
    float mean = tot * (1.0f / DD);
    __syncthreads();

    float dx0 = xv.x - mean, dx1 = xv.y - mean, dx2 = xv.z - mean, dx3 = xv.w - mean;
    float s2 = dx0*dx0 + dx1*dx1 + dx2*dx2 + dx3*dx3;
    #pragma unroll
    for (int o = 16; o > 0; o >>= 1) s2 += __shfl_xor_sync(0xffffffffu, s2, o);
    if ((tid & 31) == 0) red[tid >> 5] = s2;
    __syncthreads();
    float tot2 = 0.f;
    #pragma unroll
    for (int i = 0; i < 8; i++) tot2 += red[i];
    float inv = rsqrtf(tot2 * (1.0f / DD) + 1e-5f);

    int c = tid * 4;
    float4 wv = *(const float4*)&w[c];
    float4 bv = *(const float4*)&b[c];
    float o0 = dx0 * inv * wv.x + bv.x;
    float o1 = dx1 * inv * wv.y + bv.y;
    float o2 = dx2 * inv * wv.z + bv.z;
    float o3 = dx3 * inv * wv.w + bv.w;
    __half h0, l0, h1, l1, h2, l2, h3, l3;
    split2(o0, h0, l0); split2(o1, h1, l1); split2(o2, h2, l2); split2(o3, h3, l3);
    size_t off = (size_t)row * DD + c;
    *(__half2*)&yh[off]     = __halves2half2(h0, h1);
    *(__half2*)&yh[off + 2] = __halves2half2(h2, h3);
    *(__half2*)&yl[off]     = __halves2half2(l0, l1);
    *(__half2*)&yl[off + 2] = __halves2half2(l2, l3);
}

// ---------------------------------------------------------------------------
// Weight conversion kernels (single fp16, vectorized x4)
// ---------------------------------------------------------------------------
__global__ void conv_kernel(const float* __restrict__ s,
                            __half* __restrict__ h, int n4)
{
    int i = blockIdx.x * blockDim.x + threadIdx.x;
    if (i >= n4) return;
    float4 v = *(const float4*)&s[i * 4];
    *(__half2*)&h[i*4]   = __halves2half2(__float2half(v.x), __float2half(v.y));
    *(__half2*)&h[i*4+2] = __halves2half2(__float2half(v.z), __float2half(v.w));
}

__global__ void pack_qkv_kernel(const float* __restrict__ wq,
                                const float* __restrict__ wk,
                                const float* __restrict__ wv,
                                __half* __restrict__ h)
{
    int i = blockIdx.x * blockDim.x + threadIdx.x;
    const int per_layer4 = QKVD * DD / 4;
    if (i >= LL * per_layer4) return;
    int lyr = i / per_layer4;
    int rem = i - lyr * per_layer4;
    int row = rem >> 8;
    int c4  = rem & 255;
    int which = row >> 10;
    int srow  = row & 1023;
    const float* src = (which == 0) ? wq : ((which == 1) ? wk : wv);
    float4 v = *(const float4*)&src[(size_t)lyr * (DD*DD) + (size_t)srow * DD + c4 * 4];
    size_t o = (size_t)i * 4;
    *(__half2*)&h[o]   = __halves2half2(__float2half(v.x), __float2half(v.y));
    *(__half2*)&h[o+2] = __halves2half2(__float2half(v.z), __float2half(v.w));
}

__global__ void transpose_wo_kernel(const float* __restrict__ wo,
                                    __half* __restrict__ h)
{
    int i = blockIdx.x * blockDim.x + threadIdx.x;
    if (i >= LL * DD * DD) return;
    int lyr = i >> 20;
    int rem = i & ((1 << 20) - 1);
    int nrow = rem >> 10;
    int kcol = rem & 1023;
    h[i] = __float2half(wo[((size_t)lyr << 20) + ((size_t)kcol << 10) + nrow]);
}

// ---------------------------------------------------------------------------
// Launch
// ---------------------------------------------------------------------------
extern "C" void kernel_launch(void* const* d_in, const int* in_sizes, int n_in,
                              void* d_out, int out_size)
{
    const int*   tokens = (const int*)  d_in[0];
    const float* emb    = (const float*)d_in[1];
    const float* ln1_w  = (const float*)d_in[2];
    const float* ln1_b  = (const float*)d_in[3];
    const float* w_q    = (const float*)d_in[4];
    const float* w_k    = (const float*)d_in[5];
    const float* w_v    = (const float*)d_in[6];
    const float* w_o    = (const float*)d_in[7];
    const float* ln2_w  = (const float*)d_in[8];
    const float* ln2_b  = (const float*)d_in[9];
    const float* w1     = (const float*)d_in[10];
    const float* b1     = (const float*)d_in[11];
    const float* w2     = (const float*)d_in[12];
    const float* b2     = (const float*)d_in[13];
    const float* ro_w   = (const float*)d_in[14];
    const float* ro_b   = (const float*)d_in[15];
    float* out = (float*)d_out;

    float *x;
    __half *qkvh, *qkvl, *xnh, *xnl, *yh, *yl, *hh, *xh;
    __half *wqkv, *wo, *w1w, *w2w, *ro;
    cudaGetSymbolAddress((void**)&x,    g_x);
    cudaGetSymbolAddress((void**)&qkvh, g_qkvh); cudaGetSymbolAddress((void**)&qkvl, g_qkvl);
    cudaGetSymbolAddress((void**)&xnh,  g_xnh);  cudaGetSymbolAddress((void**)&xnl, g_xnl);
    cudaGetSymbolAddress((void**)&yh,   g_yh);   cudaGetSymbolAddress((void**)&yl,  g_yl);
    cudaGetSymbolAddress((void**)&hh,   g_hh);
    cudaGetSymbolAddress((void**)&xh,   g_xh);
    cudaGetSymbolAddress((void**)&wqkv, g_wqkv);
    cudaGetSymbolAddress((void**)&wo,   g_wo);
    cudaGetSymbolAddress((void**)&w1w,  g_w1);
    cudaGetSymbolAddress((void**)&w2w,  g_w2);
    cudaGetSymbolAddress((void**)&ro,   g_ro);

    cudaFuncSetAttribute((const void*)gemm_mma<false,false,false,true,true,true>,
                         cudaFuncAttributeMaxDynamicSharedMemorySize, SMEM_B);
    cudaFuncSetAttribute((const void*)gemm_mma<false,false,true,false,false,true>,
                         cudaFuncAttributeMaxDynamicSharedMemorySize, SMEM_B);
    cudaFuncSetAttribute((const void*)gemm_mma<true,true,false,true,false,true>,
                         cudaFuncAttributeMaxDynamicSharedMemorySize, SMEM_B);
    cudaFuncSetAttribute((const void*)gemm_mma<true,false,true,false,false,false>,
                         cudaFuncAttributeMaxDynamicSharedMemorySize, SMEM_B);
    cudaFuncSetAttribute((const void*)gemm_mma<true,false,true,true,false,false>,
                         cudaFuncAttributeMaxDynamicSharedMemorySize, SMEM_B);
    cudaFuncSetAttribute((const void*)gemm_mma<true,false,false,false,false,false>,
                         cudaFuncAttributeMaxDynamicSharedMemorySize, SMEM_B);
    cudaFuncSetAttribute((const void*)attn_mma,
                         cudaFuncAttributeMaxDynamicSharedMemorySize, AT_SMEM);

    // grid: x = M-block (fast), y = N-block (slow)
    const dim3 gQKV(MM/128, QKVD/128);    // 32 x 24
    const dim3 gD  (MM/128, DD/128);      // 32 x 8
    const dim3 gH  (MM/128, HDIM/128);    // 32 x 32
    const dim3 gV  (MM/128, VV/128);      // 32 x 250
    const dim3 gA  (TT/64, BB*HH);        // 32 x 32

    pack_qkv_kernel<<<(LL*QKVD*DD/4 + 255)/256, 256>>>(w_q, w_k, w_v, wqkv);
    embed_ln_kernel<<<MM, 256>>>(tokens, emb, ln1_w, ln1_b, x, xnh, xnl);
    transpose_wo_kernel<<<(LL*DD*DD + 255)/256, 256>>>(w_o, wo);
    gemm_mma<false,false,false,true,true,true><<<gQKV, 128, SMEM_B>>>(
        xnh, xnl, wqkv, nullptr, nullptr, qkvh, qkvl, MM, QKVD, DD);
    conv_kernel<<<(LL*HDIM*DD/4 + 255)/256, 256>>>(w1, w1w, LL*HDIM*DD/4);
    conv_kernel<<<(LL*DD*HDIM/4 + 255)/256, 256>>>(w2, w2w, LL*DD*HDIM/4);
    conv_kernel<<<(VV*DD/4 + 255)/256, 256>>>(ro_w, ro, VV*DD/4);

    for (int l = 0; l < LL; l++) {
        const __half* wqkv_l = wqkv + (size_t)l * QKVD * DD;
        const __half* wo_l   = wo   + (size_t)l * DD * DD;
        const __half* w1_l   = w1w  + (size_t)l * HDIM * DD;
        const __half* w2_l   = w2w  + (size_t)l * DD * HDIM;

        if (l > 0) {
            ln_split_kernel<<<MM, 256>>>(x, xnh, xnl, ln1_w + (size_t)l*DD, ln1_b + (size_t)l*DD);
            gemm_mma<false,false,false,true,true,true><<<gQKV, 128, SMEM_B>>>(
                xnh, xnl, wqkv_l, nullptr, nullptr, qkvh, qkvl, MM, QKVD, DD);
        }

        attn_mma<<<gA, 128, AT_SMEM>>>(qkvh, qkvl, yh, yl);

        // x += y @ wo   (2-term A: attention output feeds all later layers)
        gemm_mma<false,false,true,false,false,true><<<gD, 128, SMEM_B>>>(
            yh, yl, wo_l, nullptr, x, nullptr, nullptr, MM, DD, DD);

        ln_split_kernel<<<MM, 256>>>(x, xnh, xnl, ln2_w + (size_t)l*DD, ln2_b + (size_t)l*DD);

        // h = relu(xn @ w1 + b1) -> fp16 hi only (w2 uses 1-term A)
        gemm_mma<true,true,false,true,false,true><<<gH, 128, SMEM_B>>>(
            xnh, xnl, w1_l, b1 + (size_t)l*HDIM, nullptr, hh, nullptr, MM, HDIM, DD);

        if (l < LL - 1) {
            // x += h @ w2 + b2 — 1-term A (h quant error ~2e-4, not amplified much)
            gemm_mma<true,false,true,false,false,false><<<gD, 128, SMEM_B>>>(
                hh, nullptr, w2_l, b2 + (size_t)l*DD, x, nullptr, nullptr, MM, DD, HDIM);
        } else {
            // last layer: also emit xh (hi-only) for the 1-term readout
            gemm_mma<true,false,true,true,false,false><<<gD, 128, SMEM_B>>>(
                hh, nullptr, w2_l, b2 + (size_t)l*DD, x, xh, nullptr, MM, DD, HDIM);
        }
    }

    // readout: out = x @ ro_w^T + ro_b — 1-term A
    gemm_mma<true,false,false,false,false,false><<<gV, 128, SMEM_B>>>(
        xh, nullptr, ro, ro_b, out, nullptr, nullptr, MM, VV, DD);
}

// round 12
// speedup vs baseline: 1.2947x; 1.1292x over previous
#include <cuda_runtime.h>
#include <cuda_fp16.h>
#include <math.h>
#include <stdint.h>

// ---------------------------------------------------------------------------
// Problem constants
// ---------------------------------------------------------------------------
#define BB   2
#define TT   2048
#define DD   1024
#define HH   16
#define HDIM 4096
#define VV   32000
#define LL   4
#define MM   (BB*TT)      // 4096 rows
#define QKVD (3*DD)       // 3072

// ---------------------------------------------------------------------------
// Static device scratch (no allocations allowed)
// ---------------------------------------------------------------------------
__device__ float g_x  [MM*DD];
__device__ __half g_qkvh[MM*QKVD], g_qkvl[MM*QKVD];
__device__ __half g_xnh[MM*DD],  g_xnl[MM*DD];
__device__ __half g_yh [MM*DD];
__device__ __half g_hh [MM*HDIM];
__device__ __half g_xh [MM*DD];
// single-term fp16 weights (recomputed every launch — weights are inputs)
__device__ __half g_wqkv[LL*QKVD*DD];
__device__ __half g_wo  [LL*DD*DD];
__device__ __half g_w1  [LL*HDIM*DD];
__device__ __half g_w2  [LL*DD*HDIM];
__device__ __half g_ro  [VV*DD];

// ---------------------------------------------------------------------------
// helpers (base-target PTX only: cp.async, ldmatrix, mma.sync)
// ---------------------------------------------------------------------------
__device__ __forceinline__ uint32_t smem_u32(const void* p) {
    uint32_t a;
    asm("{ .reg .u64 t; cvta.to.shared.u64 t, %1; cvt.u32.u64 %0, t; }"
        : "=r"(a) : "l"(p));
    return a;
}
__device__ __forceinline__ void cp16(uint32_t dst, const void* src) {
    asm volatile("cp.async.cg.shared.global [%0], [%1], 16;" :: "r"(dst), "l"(src));
}
#define CP_COMMIT()  asm volatile("cp.async.commit_group;" ::: "memory")
#define CP_WAIT0()   asm volatile("cp.async.wait_group 0;" ::: "memory")
#define CP_WAIT1()   asm volatile("cp.async.wait_group 1;" ::: "memory")

__device__ __forceinline__ void ldsm4(uint32_t& r0, uint32_t& r1,
                                      uint32_t& r2, uint32_t& r3, uint32_t addr) {
    asm volatile("ldmatrix.sync.aligned.m8n8.x4.shared.b16 {%0,%1,%2,%3}, [%4];"
                 : "=r"(r0), "=r"(r1), "=r"(r2), "=r"(r3) : "r"(addr));
}
__device__ __forceinline__ void ldsm4t(uint32_t& r0, uint32_t& r1,
                                       uint32_t& r2, uint32_t& r3, uint32_t addr) {
    asm volatile("ldmatrix.sync.aligned.m8n8.x4.trans.shared.b16 {%0,%1,%2,%3}, [%4];"
                 : "=r"(r0), "=r"(r1), "=r"(r2), "=r"(r3) : "r"(addr));
}
__device__ __forceinline__ void mma16816(float* d, const uint32_t* a, const uint32_t* b) {
    asm volatile("mma.sync.aligned.m16n8k16.row.col.f32.f16.f16.f32 "
        "{%0,%1,%2,%3}, {%4,%5,%6,%7}, {%8,%9}, {%0,%1,%2,%3};"
        : "+f"(d[0]), "+f"(d[1]), "+f"(d[2]), "+f"(d[3])
        : "r"(a[0]), "r"(a[1]), "r"(a[2]), "r"(a[3]), "r"(b[0]), "r"(b[1]));
}
__device__ __forceinline__ void split2(float v, __half& h, __half& l) {
    h = __float2half(v);
    l = __float2half(v - __half2float(h));
}
__device__ __forceinline__ uint32_t pack2h(__half a, __half b) {
    __half2 hp = __halves2half2(a, b);
    return *(uint32_t*)&hp;
}

// ---------------------------------------------------------------------------
// HMMA GEMM: C[M,N] (+)= A[M,K] * B^T, B stored [N,K] fp16.
// TWOA=1: A = Ah + Al (2-term split). TWOA=0: A = Ah only.
// SPLIT: write fp16-hi output Ch; SPLITLO additionally writes Cl.
// CTA 128x128, 128 threads (4 warps 2x2, 64x64 tiles), KC=32, 3 stages,
// 90KB smem -> 2 CTAs/SM.  (R9 config — best measured; mma.sync rate cap.)
// grid.x = M-block (fast), grid.y = N-block (slow) -> weight L2 reuse.
// ---------------------------------------------------------------------------
#define STAGES  3
#define KC      32
#define PITCH   80u
#define A_TILE  (128u * PITCH)
#define STAGE_B (3u * A_TILE)
#define SMEM_B  (STAGES * STAGE_B)     // 92160

template<bool BIAS, bool RELU, bool ACCUM, bool SPLIT, bool SPLITLO, bool TWOA>
__global__ __launch_bounds__(128, 2)
void gemm_mma(const __half* __restrict__ Ah, const __half* __restrict__ Al,
              const __half* __restrict__ Bh,
              const float* __restrict__ bias,
              float* __restrict__ C,
              __half* __restrict__ Ch, __half* __restrict__ Cl,
              int M, int N, int K)
{
    extern __shared__ char smem_raw[];
    const uint32_t sb = smem_u32(smem_raw);

    const int tid  = threadIdx.x;
    const int wid  = tid >> 5;
    const int lane = tid & 31;
    const int row0 = blockIdx.x * 128;
    const int col0 = blockIdx.y * 128;
    const int NC   = K / KC;

    auto load_stage = [&](int s) {
        const uint32_t stg = sb + (uint32_t)(s % STAGES) * STAGE_B;
        const int k0 = s * KC;
        const int a_iters = TWOA ? 8 : 4;
        #pragma unroll
        for (int i = 0; i < 8; i++) {
            if (i >= a_iters) break;
            int f = i * 128 + tid;
            int sub = f >> 9;                 // 0:Ah 1:Al
            int rem = f & 511;
            int r = rem >> 2, c = rem & 3;
            const __half* src = ((sub == 0) ? Ah : Al)
                              + (size_t)(row0 + r) * K + k0 + c * 8;
            cp16(stg + (uint32_t)sub * A_TILE + (uint32_t)r * PITCH + c * 16, src);
        }
        #pragma unroll
        for (int i = 0; i < 4; i++) {
            int f = i * 128 + tid;
            int r = f >> 2, c = f & 3;
            const __half* src = Bh + (size_t)(col0 + r) * K + k0 + c * 8;
            cp16(stg + 2u*A_TILE + (uint32_t)r * PITCH + c * 16, src);
        }
        CP_COMMIT();
    };

    load_stage(0);
    if (NC > 1) load_stage(1);

    const int wm = wid >> 1;
    const int wn = wid & 1;

    float acc[4][8][4];
    #pragma unroll
    for (int a = 0; a < 4; a++)
        #pragma unroll
        for (int b = 0; b < 8; b++)
            #pragma unroll
            for (int c = 0; c < 4; c++) acc[a][b][c] = 0.f;

    for (int i = 0; i < NC; i++) {
        if (i < NC - 1) CP_WAIT1(); else CP_WAIT0();
        __syncthreads();
        if (i + 2 < NC) load_stage(i + 2);

        const uint32_t stg  = sb + (uint32_t)(i % STAGES) * STAGE_B;
        const uint32_t ah_b = stg;
        const uint32_t al_b = stg + A_TILE;
        const uint32_t bh_b = stg + 2u*A_TILE;

        #pragma unroll
        for (int ks = 0; ks < 2; ks++) {
            uint32_t ah[4][4], al[4][4], bf[8][2];
            const uint32_t a_coff = (uint32_t)ks * 32 + ((lane >> 4) << 4);
            #pragma unroll
            for (int mi = 0; mi < 4; mi++) {
                uint32_t r = (uint32_t)(wm * 64 + mi * 16 + (lane & 15));
                ldsm4(ah[mi][0], ah[mi][1], ah[mi][2], ah[mi][3], ah_b + r * PITCH + a_coff);
                if (TWOA)
                    ldsm4(al[mi][0], al[mi][1], al[mi][2], al[mi][3], al_b + r * PITCH + a_coff);
            }
            const uint32_t b_coff = (uint32_t)ks * 32 + (((lane >> 3) & 1) << 4);
            #pragma unroll
            for (int g = 0; g < 4; g++) {
                uint32_t r = (uint32_t)(wn * 64 + g * 16 + (lane & 7) + ((lane >> 4) << 3));
                ldsm4(bf[2*g][0], bf[2*g][1], bf[2*g+1][0], bf[2*g+1][1], bh_b + r * PITCH + b_coff);
            }
            #pragma unroll
            for (int mi = 0; mi < 4; mi++)
                #pragma unroll
                for (int ni = 0; ni < 8; ni++) {
                    mma16816(acc[mi][ni], ah[mi], bf[ni]);
                    if (TWOA) mma16816(acc[mi][ni], al[mi], bf[ni]);
                }
        }
    }

    #pragma unroll
    for (int mi = 0; mi < 4; mi++) {
        #pragma unroll
        for (int rg = 0; rg < 2; rg++) {
            int r = row0 + wm * 64 + mi * 16 + (lane >> 2) + rg * 8;
            #pragma unroll
            for (int ni = 0; ni < 8; ni++) {
                int c = col0 + wn * 64 + ni * 8 + (lane & 3) * 2;
                float v0 = acc[mi][ni][rg * 2 + 0];
                float v1 = acc[mi][ni][rg * 2 + 1];
                if (BIAS)  { v0 += bias[c]; v1 += bias[c + 1]; }
                if (RELU)  { v0 = fmaxf(v0, 0.f); v1 = fmaxf(v1, 0.f); }
                if (ACCUM) {
                    float2 o = *(const float2*)&C[(size_t)r * N + c];
                    v0 += o.x; v1 += o.y;
                }
                if (SPLIT) {
                    __half h0, l0, h1, l1;
                    split2(v0, h0, l0); split2(v1, h1, l1);
                    *(__half2*)&Ch[(size_t)r * N + c] = __halves2half2(h0, h1);
                    if (SPLITLO)
                        *(__half2*)&Cl[(size_t)r * N + c] = __halves2half2(l0, l1);
                } else {
                    *(float2*)&C[(size_t)r * N + c] = make_float2(v0, v1);
                }
            }
        }
    }
}

// ---------------------------------------------------------------------------
// Tensor-core causal flash attention over split-fp16 qkv [M, 3072].
// Output: fp16-hi only (wo GEMM uses 1-term A).
// ---------------------------------------------------------------------------
#define AT_PITCH 144u
#define AT_TILE  (64u * AT_PITCH)
#define AT_STAGE (4u * AT_TILE)
#define AT_SMEM  (2u * AT_STAGE)      // 73728

__global__ __launch_bounds__(128, 2)
void attn_mma(const __half* __restrict__ QKVh, const __half* __restrict__ QKVl,
              __half* __restrict__ Yh)
{
    extern __shared__ char smem_raw[];
    const uint32_t sb = smem_u32(smem_raw);

    const int tid  = threadIdx.x;
    const int wid  = tid >> 5;
    const int lane = tid & 31;
    const int bh = blockIdx.y;
    const int b  = bh >> 4;
    const int h  = bh & 15;
    const int qt = (int)(gridDim.x - 1 - blockIdx.x);
    const int qrow = b * TT + qt * 64;

    auto load_kv = [&](int st, int stile) {
        const uint32_t stg = sb + (uint32_t)st * AT_STAGE;
        const int srow = b * TT + stile * 64;
        #pragma unroll
        for (int i = 0; i < 16; i++) {
            int f = i * 128 + tid;
            int sub = f >> 9;
            int rem = f & 511;
            int r = rem >> 3, c = rem & 7;
            int colbase = ((sub < 2) ? DD : 2*DD) + h * 64;
            const __half* src = ((sub & 1) ? QKVl : QKVh)
                              + (size_t)(srow + r) * QKVD + colbase + c * 8;
            cp16(stg + (uint32_t)sub * AT_TILE + (uint32_t)r * AT_PITCH + c * 16, src);
        }
        CP_COMMIT();
    };

    load_kv(0, 0);
    {
        const uint32_t qstg = sb + AT_STAGE;
        #pragma unroll
        for (int i = 0; i < 8; i++) {
            int f = i * 128 + tid;
            int sub = f >> 9;
            int rem = f & 511;
            int r = rem >> 3, c = rem & 7;
            const __half* src = (sub ? QKVl : QKVh)
                              + (size_t)(qrow + r) * QKVD + h * 64 + c * 8;
            cp16(qstg + (uint32_t)sub * AT_TILE + (uint32_t)r * AT_PITCH + c * 16, src);
        }
        CP_COMMIT();
    }
    CP_WAIT0();
    __syncthreads();

    uint32_t qf_h[4][4], qf_l[4][4];
    {
        const uint32_t qstg = sb + AT_STAGE;
        uint32_t r = (uint32_t)(wid * 16 + (lane & 15));
        #pragma unroll
        for (int ks = 0; ks < 4; ks++) {
            uint32_t coff = (uint32_t)ks * 32 + ((lane >> 4) << 4);
            ldsm4(qf_h[ks][0], qf_h[ks][1], qf_h[ks][2], qf_h[ks][3],
                  qstg + r * AT_PITCH + coff);
            ldsm4(qf_l[ks][0], qf_l[ks][1], qf_l[ks][2], qf_l[ks][3],
                  qstg + AT_TILE + r * AT_PITCH + coff);
        }
    }
    __syncthreads();
    if (qt >= 1) load_kv(1, 1);

    float yacc[8][4];
    #pragma unroll
    for (int i = 0; i < 8; i++)
        #pragma unroll
        for (int j = 0; j < 4; j++) yacc[i][j] = 0.f;
    float m0 = -1e30f, m1 = -1e30f, l0 = 0.f, l1 = 0.f;

    for (int st = 0; st <= qt; st++) {
        if (st < qt) CP_WAIT1(); else CP_WAIT0();
        __syncthreads();
        const uint32_t stg = sb + (uint32_t)(st & 1) * AT_STAGE;

        float sacc[8][4];
        #pragma unroll
        for (int i = 0; i < 8; i++)
            #pragma unroll
            for (int j = 0; j < 4; j++) sacc[i][j] = 0.f;

        const uint32_t kb_h = stg;
        const uint32_t kb_l = stg + AT_TILE;
        #pragma unroll
        for (int ks = 0; ks < 4; ks++) {
            const uint32_t coff = (uint32_t)ks * 32 + (((lane >> 3) & 1) << 4);
            #pragma unroll
            for (int nbp = 0; nbp < 4; nbp++) {
                uint32_t r = (uint32_t)(nbp * 16 + (lane & 7) + ((lane >> 4) << 3));
                uint32_t kh[4], kl[4];
                ldsm4(kh[0], kh[1], kh[2], kh[3], kb_h + r * AT_PITCH + coff);
                mma16816(sacc[2*nbp],   qf_h[ks], kh + 0);
                mma16816(sacc[2*nbp+1], qf_h[ks], kh + 2);
                mma16816(sacc[2*nbp],   qf_l[ks], kh + 0);
                mma16816(sacc[2*nbp+1], qf_l[ks], kh + 2);
                ldsm4(kl[0], kl[1], kl[2], kl[3], kb_l + r * AT_PITCH + coff);
                mma16816(sacc[2*nbp],   qf_h[ks], kl + 0);
                mma16816(sacc[2*nbp+1], qf_h[ks], kl + 2);
            }
        }

        #pragma unroll
        for (int ni = 0; ni < 8; ni++)
            #pragma unroll
            for (int j = 0; j < 4; j++) sacc[ni][j] *= 0.125f;

        if (st == qt) {
            int q0 = wid * 16 + (lane >> 2);
            #pragma unroll
            for (int ni = 0; ni < 8; ni++) {
                int s0c = ni * 8 + 2 * (lane & 3);
                if (s0c     > q0)     sacc[ni][0] = -1e30f;
                if (s0c + 1 > q0)     sacc[ni][1] = -1e30f;
                if (s0c     > q0 + 8) sacc[ni][2] = -1e30f;
                if (s0c + 1 > q0 + 8) sacc[ni][3] = -1e30f;
            }
        }

        float mx0 = -1e30f, mx1 = -1e30f;
        #pragma unroll
        for (int ni = 0; ni < 8; ni++) {
            mx0 = fmaxf(mx0, fmaxf(sacc[ni][0], sacc[ni][1]));
            mx1 = fmaxf(mx1, fmaxf(sacc[ni][2], sacc[ni][3]));
        }
        mx0 = fmaxf(mx0, __shfl_xor_sync(0xffffffffu, mx0, 1));
        mx0 = fmaxf(mx0, __shfl_xor_sync(0xffffffffu, mx0, 2));
        mx1 = fmaxf(mx1, __shfl_xor_sync(0xffffffffu, mx1, 1));
        mx1 = fmaxf(mx1, __shfl_xor_sync(0xffffffffu, mx1, 2));

        float mn0 = fmaxf(m0, mx0), mn1 = fmaxf(m1, mx1);
        float c0 = __expf(m0 - mn0), c1 = __expf(m1 - mn1);
        l0 *= c0; l1 *= c1;
        #pragma unroll
        for (int db = 0; db < 8; db++) {
            yacc[db][0] *= c0; yacc[db][1] *= c0;
            yacc[db][2] *= c1; yacc[db][3] *= c1;
        }

        uint32_t pf_h[4][4], pf_l[4][4];
        float s0 = 0.f, s1 = 0.f;
        #pragma unroll
        for (int ni = 0; ni < 8; ni++) {
            float p0 = __expf(sacc[ni][0] - mn0);
            float p1 = __expf(sacc[ni][1] - mn0);
            float p2 = __expf(sacc[ni][2] - mn1);
            float p3 = __expf(sacc[ni][3] - mn1);
            s0 += p0 + p1; s1 += p2 + p3;
            __half h0, lo0, h1, lo1, h2, lo2, h3, lo3;
            split2(p0, h0, lo0); split2(p1, h1, lo1);
            split2(p2, h2, lo2); split2(p3, h3, lo3);
            int ks = ni >> 1;
            if ((ni & 1) == 0) {
                pf_h[ks][0] = pack2h(h0, h1);  pf_h[ks][1] = pack2h(h2, h3);
                pf_l[ks][0] = pack2h(lo0, lo1); pf_l[ks][1] = pack2h(lo2, lo3);
            } else {
                pf_h[ks][2] = pack2h(h0, h1);  pf_h[ks][3] = pack2h(h2, h3);
                pf_l[ks][2] = pack2h(lo0, lo1); pf_l[ks][3] = pack2h(lo2, lo3);
            }
        }
        s0 += __shfl_xor_sync(0xffffffffu, s0, 1);
        s0 += __shfl_xor_sync(0xffffffffu, s0, 2);
        s1 += __shfl_xor_sync(0xffffffffu, s1, 1);
        s1 += __shfl_xor_sync(0xffffffffu, s1, 2);
        l0 += s0; l1 += s1;
        m0 = mn0; m1 = mn1;

        const uint32_t vb_h = stg + 2u * AT_TILE;
        const uint32_t vb_l = stg + 3u * AT_TILE;
        #pragma unroll
        for (int ks = 0; ks < 4; ks++) {
            #pragma unroll
            for (int dbp = 0; dbp < 4; dbp++) {
                uint32_t raddr = (uint32_t)(ks * 16 + (lane & 15)) * AT_PITCH
                               + (uint32_t)dbp * 32 + ((lane >> 4) << 4);
                uint32_t vh[4], vl[4];
                ldsm4t(vh[0], vh[1], vh[2], vh[3], vb_h + raddr);
                mma16816(yacc[2*dbp],   pf_h[ks], vh + 0);
                mma16816(yacc[2*dbp+1], pf_h[ks], vh + 2);
                mma16816(yacc[2*dbp],   pf_l[ks], vh + 0);
                mma16816(yacc[2*dbp+1], pf_l[ks], vh + 2);
                ldsm4t(vl[0], vl[1], vl[2], vl[3], vb_l + raddr);
                mma16816(yacc[2*dbp],   pf_h[ks], vl + 0);
                mma16816(yacc[2*dbp+1], pf_h[ks], vl + 2);
            }
        }

        if (st + 2 <= qt) {
            __syncthreads();
            load_kv(st & 1, st + 2);
        }
    }

    float inv0 = 1.f / l0, inv1 = 1.f / l1;
    int r0g = qrow + wid * 16 + (lane >> 2);
    size_t base0 = (size_t)r0g * DD + h * 64;
    size_t base1 = base0 + (size_t)8 * DD;
    #pragma unroll
    for (int db = 0; db < 8; db++) {
        int cc = db * 8 + 2 * (lane & 3);
        *(__half2*)&Yh[base0 + cc] = __halves2half2(
            __float2half(yacc[db][0] * inv0), __float2half(yacc[db][1] * inv0));
        *(__half2*)&Yh[base1 + cc] = __halves2half2(
            __float2half(yacc[db][2] * inv1), __float2half(yacc[db][3] * inv1));
    }
}

// ---------------------------------------------------------------------------
// Fused embedding + positional encoding + LayerNorm(ln1, layer 0).
// ---------------------------------------------------------------------------
__global__ __launch_bounds__(256) void embed_ln_kernel(const int* __restrict__ tokens,
                                                       const float* __restrict__ emb,
                                                       const float* __restrict__ w,
                                                       const float* __restrict__ b,
                                                       float* __restrict__ x,
                                                       __half* __restrict__ yh,
                                                       __half* __restrict__ yl)
{
    __shared__ float red[8];
    int row = blockIdx.x;
    int tid = threadIdx.x;
    int bb  = row >> 11;
    int t   = row & (TT - 1);
    int tok = (t == 0) ? 0 : tokens[bb * TT + t - 1];

    int c = tid * 4;
    float v[4];
    #pragma unroll
    for (int j = 0; j < 4; j++) {
        int d = c + j;
        int k = d & 1;
        double e = (double)(d - k) / (double)DD;
        float freq = (float)exp(-e * 11.512925464970229);
        float arg = (float)t * freq + 1.5707963267948966f * (float)k;
        v[j] = emb[(size_t)tok * DD + d] + sinf(arg);
    }
    *(float4*)&x[(size_t)row * DD + c] = make_float4(v[0], v[1], v[2], v[3]);

    float s = v[0] + v[1] + v[2] + v[3];
    #pragma unroll
    for (int o = 16; o > 0; o >>= 1) s += __shfl_xor_sync(0xffffffffu, s, o);
    if ((tid & 31) == 0) red[tid >> 5] = s;
    __syncthreads();
    float tot = 0.f;
    #pragma unroll
    for (int i = 0; i < 8; i++) tot += red[i];
    float mean = tot * (1.0f / DD);
    __syncthreads();

    float dx0 = v[0]-mean, dx1 = v[1]-mean, dx2 = v[2]-mean, dx3 = v[3]-mean;
    float s2 = dx0*dx0 + dx1*dx1 + dx2*dx2 + dx3*dx3;
    #pragma unroll
    for (int o = 16; o > 0; o >>= 1) s2 += __shfl_xor_sync(0xffffffffu, s2, o);
    if ((tid & 31) == 0) red[tid >> 5] = s2;
    __syncthreads();
    float tot2 = 0.f;
    #pragma unroll
    for (int i = 0; i < 8; i++) tot2 += red[i];
    float inv = rsqrtf(tot2 * (1.0f / DD) + 1e-5f);

    float4 wv = *(const float4*)&w[c];
    float4 bv = *(const float4*)&b[c];
    float o0 = dx0 * inv * wv.x + bv.x;
    float o1 = dx1 * inv * wv.y + bv.y;
    float o2 = dx2 * inv * wv.z + bv.z;
    float o3 = dx3 * inv * wv.w + bv.w;
    __half h0, l0, h1, l1, h2, l2, h3, l3;
    split2(o0, h0, l0); split2(o1, h1, l1); split2(o2, h2, l2); split2(o3, h3, l3);
    size_t off = (size_t)row * DD + c;
    *(__half2*)&yh[off]     = __halves2half2(h0, h1);
    *(__half2*)&yh[off + 2] = __halves2half2(h2, h3);
    *(__half2*)&yl[off]     = __halves2half2(l0, l1);
    *(__half2*)&yl[off + 2] = __halves2half2(l2, l3);
}

// ---------------------------------------------------------------------------
// LayerNorm -> fp16 output; LO controls whether the lo term is written.
// ---------------------------------------------------------------------------
template<bool LO>
__global__ __launch_bounds__(256) void ln_split_kernel(const float* __restrict__ x,
                                                       __half* __restrict__ yh,
                                                       __half* __restrict__ yl,
                                                       const float* __restrict__ w,
                                                       const float* __restrict__ b)
{
    __shared__ float red[8];
    int row = blockIdx.x;
    int tid = threadIdx.x;
    const float* xr = x + (size_t)row * DD;
    float4 xv = *(const float4*)&xr[tid * 4];

    float s = xv.x + xv.y + xv.z + xv.w;
    #pragma unroll
    for (int o = 16; o > 0; o >>= 1) s += __shfl_xor_sync(0xffffffffu, s, o);
    if ((tid & 31) == 0) red[tid >> 5] = s;
    __syncthreads();
    float tot = 0.f;
    #pragma unroll
    for (int i = 0; i < 8; i++) tot += red[i];
    float mean = tot * (1.0f / DD);
    __syncthreads();

    float dx0 = xv.x - mean, dx1 = xv.y - mean, dx2 = xv.z - mean, dx3 = xv.w - mean;
    float s2 = dx0*dx0 + dx1*dx1 + dx2*dx2 + dx3*dx3;
    #pragma unroll
    for (int o = 16; o > 0; o >>= 1) s2 += __shfl_xor_sync(0xffffffffu, s2, o);
    if ((tid & 31) == 0) red[tid >> 5] = s2;
    __syncthreads();
    float tot2 = 0.f;
    #pragma unroll
    for (int i = 0; i < 8; i++) tot2 += red[i];
    float inv = rsqrtf(tot2 * (1.0f / DD) + 1e-5f);

    int c = tid * 4;
    float4 wv = *(const float4*)&w[c];
    float4 bv = *(const float4*)&b[c];
    float o0 = dx0 * inv * wv.x + bv.x;
    float o1 = dx1 * inv * wv.y + bv.y;
    float o2 = dx2 * inv * wv.z + bv.z;
    float o3 = dx3 * inv * wv.w + bv.w;
    size_t off = (size_t)row * DD + c;
    if (LO) {
        __half h0, l0, h1, l1, h2, l2, h3, l3;
        split2(o0, h0, l0); split2(o1, h1, l1); split2(o2, h2, l2); split2(o3, h3, l3);
        *(__half2*)&yh[off]     = __halves2half2(h0, h1);
        *(__half2*)&yh[off + 2] = __halves2half2(h2, h3);
        *(__half2*)&yl[off]     = __halves2half2(l0, l1);
        *(__half2*)&yl[off + 2] = __halves2half2(l2, l3);
    } else {
        *(__half2*)&yh[off]     = __halves2half2(__float2half(o0), __float2half(o1));
        *(__half2*)&yh[off + 2] = __halves2half2(__float2half(o2), __float2half(o3));
    }
}

// ---------------------------------------------------------------------------
// Weight conversion kernels (single fp16, vectorized x4)
// ---------------------------------------------------------------------------
__global__ void conv_kernel(const float* __restrict__ s,
                            __half* __restrict__ h, int n4)
{
    int i = blockIdx.x * blockDim.x + threadIdx.x;
    if (i >= n4) return;
    float4 v = *(const float4*)&s[i * 4];
    *(__half2*)&h[i*4]   = __halves2half2(__float2half(v.x), __float2half(v.y));
    *(__half2*)&h[i*4+2] = __halves2half2(__float2half(v.z), __float2half(v.w));
}

__global__ void pack_qkv_kernel(const float* __restrict__ wq,
                                const float* __restrict__ wk,
                                const float* __restrict__ wv,
                                __half* __restrict__ h)
{
    int i = blockIdx.x * blockDim.x + threadIdx.x;
    const int per_layer4 = QKVD * DD / 4;
    if (i >= LL * per_layer4) return;
    int lyr = i / per_layer4;
    int rem = i - lyr * per_layer4;
    int row = rem >> 8;
    int c4  = rem & 255;
    int which = row >> 10;
    int srow  = row & 1023;
    const float* src = (which == 0) ? wq : ((which == 1) ? wk : wv);
    float4 v = *(const float4*)&src[(size_t)lyr * (DD*DD) + (size_t)srow * DD + c4 * 4];
    size_t o = (size_t)i * 4;
    *(__half2*)&h[o]   = __halves2half2(__float2half(v.x), __float2half(v.y));
    *(__half2*)&h[o+2] = __halves2half2(__float2half(v.z), __float2half(v.w));
}

__global__ void transpose_wo_kernel(const float* __restrict__ wo,
                                    __half* __restrict__ h)
{
    int i = blockIdx.x * blockDim.x + threadIdx.x;
    if (i >= LL * DD * DD) return;
    int lyr = i >> 20;
    int rem = i & ((1 << 20) - 1);
    int nrow = rem >> 10;
    int kcol = rem & 1023;
    h[i] = __float2half(wo[((size_t)lyr << 20) + ((size_t)kcol << 10) + nrow]);
}

// ---------------------------------------------------------------------------
// Launch
// ---------------------------------------------------------------------------
extern "C" void kernel_launch(void* const* d_in, const int* in_sizes, int n_in,
                              void* d_out, int out_size)
{
    const int*   tokens = (const int*)  d_in[0];
    const float* emb    = (const float*)d_in[1];
    const float* ln1_w  = (const float*)d_in[2];
    const float* ln1_b  = (const float*)d_in[3];
    const float* w_q    = (const float*)d_in[4];
    const float* w_k    = (const float*)d_in[5];
    const float* w_v    = (const float*)d_in[6];
    const float* w_o    = (const float*)d_in[7];
    const float* ln2_w  = (const float*)d_in[8];
    const float* ln2_b  = (const float*)d_in[9];
    const float* w1     = (const float*)d_in[10];
    const float* b1     = (const float*)d_in[11];
    const float* w2     = (const float*)d_in[12];
    const float* b2     = (const float*)d_in[13];
    const float* ro_w   = (const float*)d_in[14];
    const float* ro_b   = (const float*)d_in[15];
    float* out = (float*)d_out;

    float *x;
    __half *qkvh, *qkvl, *xnh, *xnl, *yh, *hh, *xh;
    __half *wqkv, *wo, *w1w, *w2w, *ro;
    cudaGetSymbolAddress((void**)&x,    g_x);
    cudaGetSymbolAddress((void**)&qkvh, g_qkvh); cudaGetSymbolAddress((void**)&qkvl, g_qkvl);
    cudaGetSymbolAddress((void**)&xnh,  g_xnh);  cudaGetSymbolAddress((void**)&xnl, g_xnl);
    cudaGetSymbolAddress((void**)&yh,   g_yh);
    cudaGetSymbolAddress((void**)&hh,   g_hh);
    cudaGetSymbolAddress((void**)&xh,   g_xh);
    cudaGetSymbolAddress((void**)&wqkv, g_wqkv);
    cudaGetSymbolAddress((void**)&wo,   g_wo);
    cudaGetSymbolAddress((void**)&w1w,  g_w1);
    cudaGetSymbolAddress((void**)&w2w,  g_w2);
    cudaGetSymbolAddress((void**)&ro,   g_ro);

    cudaFuncSetAttribute((const void*)gemm_mma<false,false,false,true,true,true>,
                         cudaFuncAttributeMaxDynamicSharedMemorySize, SMEM_B);
    cudaFuncSetAttribute((const void*)gemm_mma<false,false,true,false,false,false>,
                         cudaFuncAttributeMaxDynamicSharedMemorySize, SMEM_B);
    cudaFuncSetAttribute((const void*)gemm_mma<true,true,false,true,false,false>,
                         cudaFuncAttributeMaxDynamicSharedMemorySize, SMEM_B);
    cudaFuncSetAttribute((const void*)gemm_mma<true,false,true,false,false,false>,
                         cudaFuncAttributeMaxDynamicSharedMemorySize, SMEM_B);
    cudaFuncSetAttribute((const void*)gemm_mma<true,false,true,true,false,false>,
                         cudaFuncAttributeMaxDynamicSharedMemorySize, SMEM_B);
    cudaFuncSetAttribute((const void*)gemm_mma<true,false,false,false,false,false>,
                         cudaFuncAttributeMaxDynamicSharedMemorySize, SMEM_B);
    cudaFuncSetAttribute((const void*)attn_mma,
                         cudaFuncAttributeMaxDynamicSharedMemorySize, AT_SMEM);

    // grid: x = M-block (fast), y = N-block (slow)
    const dim3 gQKV(MM/128, QKVD/128);    // 32 x 24
    const dim3 gD  (MM/128, DD/128);      // 32 x 8
    const dim3 gH  (MM/128, HDIM/128);    // 32 x 32
    const dim3 gV  (MM/128, VV/128);      // 32 x 250
    const dim3 gA  (TT/64, BB*HH);        // 32 x 32

    pack_qkv_kernel<<<(LL*QKVD*DD/4 + 255)/256, 256>>>(w_q, w_k, w_v, wqkv);
    embed_ln_kernel<<<MM, 256>>>(tokens, emb, ln1_w, ln1_b, x, xnh, xnl);
    transpose_wo_kernel<<<(LL*DD*DD + 255)/256, 256>>>(w_o, wo);
    gemm_mma<false,false,false,true,true,true><<<gQKV, 128, SMEM_B>>>(
        xnh, xnl, wqkv, nullptr, nullptr, qkvh, qkvl, MM, QKVD, DD);
    conv_kernel<<<(LL*HDIM*DD/4 + 255)/256, 256>>>(w1, w1w, LL*HDIM*DD/4);
    conv_kernel<<<(LL*DD*HDIM/4 + 255)/256, 256>>>(w2, w2w, LL*DD*HDIM/4);
    conv_kernel<<<(VV*DD/4 + 255)/256, 256>>>(ro_w, ro, VV*DD/4);

    for (int l = 0; l < LL; l++) {
        const __half* wqkv_l = wqkv + (size_t)l * QKVD * DD;
        const __half* wo_l   = wo   + (size_t)l * DD * DD;
        const __half* w1_l   = w1w  + (size_t)l * HDIM * DD;
        const __half* w2_l   = w2w  + (size_t)l * DD * HDIM;

        if (l > 0) {
            // ln1 -> hi+lo (QKV stays 2-term: attention path is error-sensitive)
            ln_split_kernel<true><<<MM, 256>>>(x, xnh, xnl,
                ln1_w + (size_t)l*DD, ln1_b + (size_t)l*DD);
            gemm_mma<false,false,false,true,true,true><<<gQKV, 128, SMEM_B>>>(
                xnh, xnl, wqkv_l, nullptr, nullptr, qkvh, qkvl, MM, QKVD, DD);
        }

        attn_mma<<<gA, 128, AT_SMEM>>>(qkvh, qkvl, yh);

        // x += y @ wo — 1-term A (y quant error attenuated in residual stream)
        gemm_mma<false,false,true,false,false,false><<<gD, 128, SMEM_B>>>(
            yh, nullptr, wo_l, nullptr, x, nullptr, nullptr, MM, DD, DD);

        // ln2 -> hi only (w1 uses 1-term A)
        ln_split_kernel<false><<<MM, 256>>>(x, xnh, nullptr,
            ln2_w + (size_t)l*DD, ln2_b + (size_t)l*DD);

        // h = relu(xn @ w1 + b1) -> fp16 hi only
        gemm_mma<true,true,false,true,false,false><<<gH, 128, SMEM_B>>>(
            xnh, nullptr, w1_l, b1 + (size_t)l*HDIM, nullptr, hh, nullptr, MM, HDIM, DD);

        if (l < LL - 1) {
            gemm_mma<true,false,true,false,false,false><<<gD, 128, SMEM_B>>>(
                hh, nullptr, w2_l, b2 + (size_t)l*DD, x, nullptr, nullptr, MM, DD, HDIM);
        } else {
            gemm_mma<true,false,true,true,false,false><<<gD, 128, SMEM_B>>>(
                hh, nullptr, w2_l, b2 + (size_t)l*DD, x, xh, nullptr, MM, DD, HDIM);
        }
    }

    // readout: out = x @ ro_w^T + ro_b — 1-term A
    gemm_mma<true,false,false,false,false,false><<<gV, 128, SMEM_B>>>(
        xh, nullptr, ro, ro_b, out, nullptr, nullptr, MM, VV, DD);
}

// round 13
// speedup vs baseline: 1.6410x; 1.2675x over previous
#include <cuda_runtime.h>
#include <cuda_fp16.h>
#include <math.h>
#include <stdint.h>

// ---------------------------------------------------------------------------
// Problem constants
// ---------------------------------------------------------------------------
#define BB   2
#define TT   2048
#define DD   1024
#define HH   16
#define HDIM 4096
#define VV   32000
#define LL   4
#define MM   (BB*TT)      // 4096 rows
#define QKVD (3*DD)       // 3072

// ---------------------------------------------------------------------------
// Static device scratch (no allocations allowed)
// ---------------------------------------------------------------------------
__device__ float g_x  [MM*DD];
__device__ __half g_qkvh[MM*QKVD];
__device__ __half g_xnh[MM*DD];
__device__ __half g_yh [MM*DD];
__device__ __half g_hh [MM*HDIM];
__device__ __half g_xh [MM*DD];
// single-term fp16 weights (recomputed every launch — weights are inputs)
__device__ __half g_wqkv[LL*QKVD*DD];
__device__ __half g_wo  [LL*DD*DD];
__device__ __half g_w1  [LL*HDIM*DD];
__device__ __half g_w2  [LL*DD*HDIM];
__device__ __half g_ro  [VV*DD];

// ---------------------------------------------------------------------------
// helpers (base-target PTX only: cp.async, ldmatrix, mma.sync)
// ---------------------------------------------------------------------------
__device__ __forceinline__ uint32_t smem_u32(const void* p) {
    uint32_t a;
    asm("{ .reg .u64 t; cvta.to.shared.u64 t, %1; cvt.u32.u64 %0, t; }"
        : "=r"(a) : "l"(p));
    return a;
}
__device__ __forceinline__ void cp16(uint32_t dst, const void* src) {
    asm volatile("cp.async.cg.shared.global [%0], [%1], 16;" :: "r"(dst), "l"(src));
}
#define CP_COMMIT()  asm volatile("cp.async.commit_group;" ::: "memory")
#define CP_WAIT0()   asm volatile("cp.async.wait_group 0;" ::: "memory")
#define CP_WAIT1()   asm volatile("cp.async.wait_group 1;" ::: "memory")

__device__ __forceinline__ void ldsm4(uint32_t& r0, uint32_t& r1,
                                      uint32_t& r2, uint32_t& r3, uint32_t addr) {
    asm volatile("ldmatrix.sync.aligned.m8n8.x4.shared.b16 {%0,%1,%2,%3}, [%4];"
                 : "=r"(r0), "=r"(r1), "=r"(r2), "=r"(r3) : "r"(addr));
}
__device__ __forceinline__ void ldsm4t(uint32_t& r0, uint32_t& r1,
                                       uint32_t& r2, uint32_t& r3, uint32_t addr) {
    asm volatile("ldmatrix.sync.aligned.m8n8.x4.trans.shared.b16 {%0,%1,%2,%3}, [%4];"
                 : "=r"(r0), "=r"(r1), "=r"(r2), "=r"(r3) : "r"(addr));
}
__device__ __forceinline__ void mma16816(float* d, const uint32_t* a, const uint32_t* b) {
    asm volatile("mma.sync.aligned.m16n8k16.row.col.f32.f16.f16.f32 "
        "{%0,%1,%2,%3}, {%4,%5,%6,%7}, {%8,%9}, {%0,%1,%2,%3};"
        : "+f"(d[0]), "+f"(d[1]), "+f"(d[2]), "+f"(d[3])
        : "r"(a[0]), "r"(a[1]), "r"(a[2]), "r"(a[3]), "r"(b[0]), "r"(b[1]));
}
__device__ __forceinline__ void split2(float v, __half& h, __half& l) {
    h = __float2half(v);
    l = __float2half(v - __half2float(h));
}
__device__ __forceinline__ uint32_t pack2h(__half a, __half b) {
    __half2 hp = __halves2half2(a, b);
    return *(uint32_t*)&hp;
}

// ---------------------------------------------------------------------------
// HMMA GEMM: C[M,N] (+)= A[M,K] * B^T, B stored [N,K] fp16.
// TWOA=1: A = Ah + Al. TWOA=0: A = Ah only (all call sites now 1-term).
// SPLIT: write fp16-hi output Ch; SPLITLO additionally writes Cl.
// CTA 128x128, 128 threads (4 warps 2x2, 64x64 tiles), KC=32, 3 stages.
// ---------------------------------------------------------------------------
#define STAGES  3
#define KC      32
#define PITCH   80u
#define A_TILE  (128u * PITCH)
#define STAGE_B (3u * A_TILE)
#define SMEM_B  (STAGES * STAGE_B)     // 92160

template<bool BIAS, bool RELU, bool ACCUM, bool SPLIT, bool SPLITLO, bool TWOA>
__global__ __launch_bounds__(128, 2)
void gemm_mma(const __half* __restrict__ Ah, const __half* __restrict__ Al,
              const __half* __restrict__ Bh,
              const float* __restrict__ bias,
              float* __restrict__ C,
              __half* __restrict__ Ch, __half* __restrict__ Cl,
              int M, int N, int K)
{
    extern __shared__ char smem_raw[];
    const uint32_t sb = smem_u32(smem_raw);

    const int tid  = threadIdx.x;
    const int wid  = tid >> 5;
    const int lane = tid & 31;
    const int row0 = blockIdx.x * 128;
    const int col0 = blockIdx.y * 128;
    const int NC   = K / KC;

    auto load_stage = [&](int s) {
        const uint32_t stg = sb + (uint32_t)(s % STAGES) * STAGE_B;
        const int k0 = s * KC;
        const int a_iters = TWOA ? 8 : 4;
        #pragma unroll
        for (int i = 0; i < 8; i++) {
            if (i >= a_iters) break;
            int f = i * 128 + tid;
            int sub = f >> 9;                 // 0:Ah 1:Al
            int rem = f & 511;
            int r = rem >> 2, c = rem & 3;
            const __half* src = ((sub == 0) ? Ah : Al)
                              + (size_t)(row0 + r) * K + k0 + c * 8;
            cp16(stg + (uint32_t)sub * A_TILE + (uint32_t)r * PITCH + c * 16, src);
        }
        #pragma unroll
        for (int i = 0; i < 4; i++) {
            int f = i * 128 + tid;
            int r = f >> 2, c = f & 3;
            const __half* src = Bh + (size_t)(col0 + r) * K + k0 + c * 8;
            cp16(stg + 2u*A_TILE + (uint32_t)r * PITCH + c * 16, src);
        }
        CP_COMMIT();
    };

    load_stage(0);
    if (NC > 1) load_stage(1);

    const int wm = wid >> 1;
    const int wn = wid & 1;

    float acc[4][8][4];
    #pragma unroll
    for (int a = 0; a < 4; a++)
        #pragma unroll
        for (int b = 0; b < 8; b++)
            #pragma unroll
            for (int c = 0; c < 4; c++) acc[a][b][c] = 0.f;

    for (int i = 0; i < NC; i++) {
        if (i < NC - 1) CP_WAIT1(); else CP_WAIT0();
        __syncthreads();
        if (i + 2 < NC) load_stage(i + 2);

        const uint32_t stg  = sb + (uint32_t)(i % STAGES) * STAGE_B;
        const uint32_t ah_b = stg;
        const uint32_t al_b = stg + A_TILE;
        const uint32_t bh_b = stg + 2u*A_TILE;

        #pragma unroll
        for (int ks = 0; ks < 2; ks++) {
            uint32_t ah[4][4], al[4][4], bf[8][2];
            const uint32_t a_coff = (uint32_t)ks * 32 + ((lane >> 4) << 4);
            #pragma unroll
            for (int mi = 0; mi < 4; mi++) {
                uint32_t r = (uint32_t)(wm * 64 + mi * 16 + (lane & 15));
                ldsm4(ah[mi][0], ah[mi][1], ah[mi][2], ah[mi][3], ah_b + r * PITCH + a_coff);
                if (TWOA)
                    ldsm4(al[mi][0], al[mi][1], al[mi][2], al[mi][3], al_b + r * PITCH + a_coff);
            }
            const uint32_t b_coff = (uint32_t)ks * 32 + (((lane >> 3) & 1) << 4);
            #pragma unroll
            for (int g = 0; g < 4; g++) {
                uint32_t r = (uint32_t)(wn * 64 + g * 16 + (lane & 7) + ((lane >> 4) << 3));
                ldsm4(bf[2*g][0], bf[2*g][1], bf[2*g+1][0], bf[2*g+1][1], bh_b + r * PITCH + b_coff);
            }
            #pragma unroll
            for (int mi = 0; mi < 4; mi++)
                #pragma unroll
                for (int ni = 0; ni < 8; ni++) {
                    mma16816(acc[mi][ni], ah[mi], bf[ni]);
                    if (TWOA) mma16816(acc[mi][ni], al[mi], bf[ni]);
                }
        }
    }

    #pragma unroll
    for (int mi = 0; mi < 4; mi++) {
        #pragma unroll
        for (int rg = 0; rg < 2; rg++) {
            int r = row0 + wm * 64 + mi * 16 + (lane >> 2) + rg * 8;
            #pragma unroll
            for (int ni = 0; ni < 8; ni++) {
                int c = col0 + wn * 64 + ni * 8 + (lane & 3) * 2;
                float v0 = acc[mi][ni][rg * 2 + 0];
                float v1 = acc[mi][ni][rg * 2 + 1];
                if (BIAS)  { v0 += bias[c]; v1 += bias[c + 1]; }
                if (RELU)  { v0 = fmaxf(v0, 0.f); v1 = fmaxf(v1, 0.f); }
                if (ACCUM) {
                    float2 o = *(const float2*)&C[(size_t)r * N + c];
                    v0 += o.x; v1 += o.y;
                }
                if (SPLIT) {
                    if (SPLITLO) {
                        __half h0, l0, h1, l1;
                        split2(v0, h0, l0); split2(v1, h1, l1);
                        *(__half2*)&Ch[(size_t)r * N + c] = __halves2half2(h0, h1);
                        *(__half2*)&Cl[(size_t)r * N + c] = __halves2half2(l0, l1);
                    } else {
                        *(__half2*)&Ch[(size_t)r * N + c] =
                            __halves2half2(__float2half(v0), __float2half(v1));
                    }
                } else {
                    *(float2*)&C[(size_t)r * N + c] = make_float2(v0, v1);
                }
            }
        }
    }
}

// ---------------------------------------------------------------------------
// Tensor-core causal flash attention, single-term fp16 qkv [M, 3072].
// Scores: Qh*Kh (1 MMA/k16). PV: Ph*Vh (1 MMA/k16). Output fp16-hi.
// KV stage = Kh | Vh (18KB), 2 stages, occupancy 3.
// ---------------------------------------------------------------------------
#define AT_PITCH 144u
#define AT_TILE  (64u * AT_PITCH)     // 9216
#define AT_STAGE (2u * AT_TILE)       // 18432: Kh | Vh
#define AT_SMEM  (2u * AT_STAGE)      // 36864

__global__ __launch_bounds__(128, 3)
void attn_mma(const __half* __restrict__ QKVh, __half* __restrict__ Yh)
{
    extern __shared__ char smem_raw[];
    const uint32_t sb = smem_u32(smem_raw);

    const int tid  = threadIdx.x;
    const int wid  = tid >> 5;
    const int lane = tid & 31;
    const int bh = blockIdx.y;
    const int b  = bh >> 4;
    const int h  = bh & 15;
    const int qt = (int)(gridDim.x - 1 - blockIdx.x);
    const int qrow = b * TT + qt * 64;

    auto load_kv = [&](int st, int stile) {
        const uint32_t stg = sb + (uint32_t)st * AT_STAGE;
        const int srow = b * TT + stile * 64;
        #pragma unroll
        for (int i = 0; i < 8; i++) {
            int f = i * 128 + tid;            // 0..1023
            int sub = f >> 9;                 // 0:K 1:V
            int rem = f & 511;
            int r = rem >> 3, c = rem & 7;
            const __half* src = QKVh + (size_t)(srow + r) * QKVD
                              + DD + sub * DD + h * 64 + c * 8;
            cp16(stg + (uint32_t)sub * AT_TILE + (uint32_t)r * AT_PITCH + c * 16, src);
        }
        CP_COMMIT();
    };

    // prologue: kv tile 0 -> stage 0; Q -> stage1 region
    load_kv(0, 0);
    {
        const uint32_t qstg = sb + AT_STAGE;
        #pragma unroll
        for (int i = 0; i < 4; i++) {
            int f = i * 128 + tid;            // 0..511
            int r = f >> 3, c = f & 7;
            const __half* src = QKVh + (size_t)(qrow + r) * QKVD + h * 64 + c * 8;
            cp16(qstg + (uint32_t)r * AT_PITCH + c * 16, src);
        }
        CP_COMMIT();
    }
    CP_WAIT0();
    __syncthreads();

    uint32_t qf_h[4][4];
    {
        const uint32_t qstg = sb + AT_STAGE;
        uint32_t r = (uint32_t)(wid * 16 + (lane & 15));
        #pragma unroll
        for (int ks = 0; ks < 4; ks++) {
            uint32_t coff = (uint32_t)ks * 32 + ((lane >> 4) << 4);
            ldsm4(qf_h[ks][0], qf_h[ks][1], qf_h[ks][2], qf_h[ks][3],
                  qstg + r * AT_PITCH + coff);
        }
    }
    __syncthreads();
    if (qt >= 1) load_kv(1, 1);

    float yacc[8][4];
    #pragma unroll
    for (int i = 0; i < 8; i++)
        #pragma unroll
        for (int j = 0; j < 4; j++) yacc[i][j] = 0.f;
    float m0 = -1e30f, m1 = -1e30f, l0 = 0.f, l1 = 0.f;

    for (int st = 0; st <= qt; st++) {
        if (st < qt) CP_WAIT1(); else CP_WAIT0();
        __syncthreads();
        const uint32_t stg = sb + (uint32_t)(st & 1) * AT_STAGE;

        float sacc[8][4];
        #pragma unroll
        for (int i = 0; i < 8; i++)
            #pragma unroll
            for (int j = 0; j < 4; j++) sacc[i][j] = 0.f;

        const uint32_t kb_h = stg;
        #pragma unroll
        for (int ks = 0; ks < 4; ks++) {
            const uint32_t coff = (uint32_t)ks * 32 + (((lane >> 3) & 1) << 4);
            #pragma unroll
            for (int nbp = 0; nbp < 4; nbp++) {
                uint32_t r = (uint32_t)(nbp * 16 + (lane & 7) + ((lane >> 4) << 3));
                uint32_t kh[4];
                ldsm4(kh[0], kh[1], kh[2], kh[3], kb_h + r * AT_PITCH + coff);
                mma16816(sacc[2*nbp],   qf_h[ks], kh + 0);
                mma16816(sacc[2*nbp+1], qf_h[ks], kh + 2);
            }
        }

        #pragma unroll
        for (int ni = 0; ni < 8; ni++)
            #pragma unroll
            for (int j = 0; j < 4; j++) sacc[ni][j] *= 0.125f;

        if (st == qt) {
            int q0 = wid * 16 + (lane >> 2);
            #pragma unroll
            for (int ni = 0; ni < 8; ni++) {
                int s0c = ni * 8 + 2 * (lane & 3);
                if (s0c     > q0)     sacc[ni][0] = -1e30f;
                if (s0c + 1 > q0)     sacc[ni][1] = -1e30f;
                if (s0c     > q0 + 8) sacc[ni][2] = -1e30f;
                if (s0c + 1 > q0 + 8) sacc[ni][3] = -1e30f;
            }
        }

        float mx0 = -1e30f, mx1 = -1e30f;
        #pragma unroll
        for (int ni = 0; ni < 8; ni++) {
            mx0 = fmaxf(mx0, fmaxf(sacc[ni][0], sacc[ni][1]));
            mx1 = fmaxf(mx1, fmaxf(sacc[ni][2], sacc[ni][3]));
        }
        mx0 = fmaxf(mx0, __shfl_xor_sync(0xffffffffu, mx0, 1));
        mx0 = fmaxf(mx0, __shfl_xor_sync(0xffffffffu, mx0, 2));
        mx1 = fmaxf(mx1, __shfl_xor_sync(0xffffffffu, mx1, 1));
        mx1 = fmaxf(mx1, __shfl_xor_sync(0xffffffffu, mx1, 2));

        float mn0 = fmaxf(m0, mx0), mn1 = fmaxf(m1, mx1);
        float c0 = __expf(m0 - mn0), c1 = __expf(m1 - mn1);
        l0 *= c0; l1 *= c1;
        #pragma unroll
        for (int db = 0; db < 8; db++) {
            yacc[db][0] *= c0; yacc[db][1] *= c0;
            yacc[db][2] *= c1; yacc[db][3] *= c1;
        }

        uint32_t pf_h[4][4];
        float s0 = 0.f, s1 = 0.f;
        #pragma unroll
        for (int ni = 0; ni < 8; ni++) {
            float p0 = __expf(sacc[ni][0] - mn0);
            float p1 = __expf(sacc[ni][1] - mn0);
            float p2 = __expf(sacc[ni][2] - mn1);
            float p3 = __expf(sacc[ni][3] - mn1);
            s0 += p0 + p1; s1 += p2 + p3;
            int ks = ni >> 1;
            uint32_t lohi = pack2h(__float2half(p0), __float2half(p1));
            uint32_t hihi = pack2h(__float2half(p2), __float2half(p3));
            if ((ni & 1) == 0) { pf_h[ks][0] = lohi; pf_h[ks][1] = hihi; }
            else               { pf_h[ks][2] = lohi; pf_h[ks][3] = hihi; }
        }
        s0 += __shfl_xor_sync(0xffffffffu, s0, 1);
        s0 += __shfl_xor_sync(0xffffffffu, s0, 2);
        s1 += __shfl_xor_sync(0xffffffffu, s1, 1);
        s1 += __shfl_xor_sync(0xffffffffu, s1, 2);
        l0 += s0; l1 += s1;
        m0 = mn0; m1 = mn1;

        const uint32_t vb_h = stg + AT_TILE;
        #pragma unroll
        for (int ks = 0; ks < 4; ks++) {
            #pragma unroll
            for (int dbp = 0; dbp < 4; dbp++) {
                uint32_t raddr = (uint32_t)(ks * 16 + (lane & 15)) * AT_PITCH
                               + (uint32_t)dbp * 32 + ((lane >> 4) << 4);
                uint32_t vh[4];
                ldsm4t(vh[0], vh[1], vh[2], vh[3], vb_h + raddr);
                mma16816(yacc[2*dbp],   pf_h[ks], vh + 0);
                mma16816(yacc[2*dbp+1], pf_h[ks], vh + 2);
            }
        }

        if (st + 2 <= qt) {
            __syncthreads();
            load_kv(st & 1, st + 2);
        }
    }

    float inv0 = 1.f / l0, inv1 = 1.f / l1;
    int r0g = qrow + wid * 16 + (lane >> 2);
    size_t base0 = (size_t)r0g * DD + h * 64;
    size_t base1 = base0 + (size_t)8 * DD;
    #pragma unroll
    for (int db = 0; db < 8; db++) {
        int cc = db * 8 + 2 * (lane & 3);
        *(__half2*)&Yh[base0 + cc] = __halves2half2(
            __float2half(yacc[db][0] * inv0), __float2half(yacc[db][1] * inv0));
        *(__half2*)&Yh[base1 + cc] = __halves2half2(
            __float2half(yacc[db][2] * inv1), __float2half(yacc[db][3] * inv1));
    }
}

// ---------------------------------------------------------------------------
// Fused embedding + positional encoding + LayerNorm(ln1, layer 0) -> fp16 hi.
// ---------------------------------------------------------------------------
__global__ __launch_bounds__(256) void embed_ln_kernel(const int* __restrict__ tokens,
                                                       const float* __restrict__ emb,
                                                       const float* __restrict__ w,
                                                       const float* __restrict__ b,
                                                       float* __restrict__ x,
                                                       __half* __restrict__ yh)
{
    __shared__ float red[8];
    int row = blockIdx.x;
    int tid = threadIdx.x;
    int bb  = row >> 11;
    int t   = row & (TT - 1);
    int tok = (t == 0) ? 0 : tokens[bb * TT + t - 1];

    int c = tid * 4;
    float v[4];
    #pragma unroll
    for (int j = 0; j < 4; j++) {
        int d = c + j;
        int k = d & 1;
        double e = (double)(d - k) / (double)DD;
        float freq = (float)exp(-e * 11.512925464970229);
        float arg = (float)t * freq + 1.5707963267948966f * (float)k;
        v[j] = emb[(size_t)tok * DD + d] + sinf(arg);
    }
    *(float4*)&x[(size_t)row * DD + c] = make_float4(v[0], v[1], v[2], v[3]);

    float s = v[0] + v[1] + v[2] + v[3];
    #pragma unroll
    for (int o = 16; o > 0; o >>= 1) s += __shfl_xor_sync(0xffffffffu, s, o);
    if ((tid & 31) == 0) red[tid >> 5] = s;
    __syncthreads();
    float tot = 0.f;
    #pragma unroll
    for (int i = 0; i < 8; i++) tot += red[i];
    float mean = tot * (1.0f / DD);
    __syncthreads();

    float dx0 = v[0]-mean, dx1 = v[1]-mean, dx2 = v[2]-mean, dx3 = v[3]-mean;
    float s2 = dx0*dx0 + dx1*dx1 + dx2*dx2 + dx3*dx3;
    #pragma unroll
    for (int o = 16; o > 0; o >>= 1) s2 += __shfl_xor_sync(0xffffffffu, s2, o);
    if ((tid & 31) == 0) red[tid >> 5] = s2;
    __syncthreads();
    float tot2 = 0.f;
    #pragma unroll
    for (int i = 0; i < 8; i++) tot2 += red[i];
    float inv = rsqrtf(tot2 * (1.0f / DD) + 1e-5f);

    float4 wv = *(const float4*)&w[c];
    float4 bv = *(const float4*)&b[c];
    float o0 = dx0 * inv * wv.x + bv.x;
    float o1 = dx1 * inv * wv.y + bv.y;
    float o2 = dx2 * inv * wv.z + bv.z;
    float o3 = dx3 * inv * wv.w + bv.w;
    size_t off = (size_t)row * DD + c;
    *(__half2*)&yh[off]     = __halves2half2(__float2half(o0), __float2half(o1));
    *(__half2*)&yh[off + 2] = __halves2half2(__float2half(o2), __float2half(o3));
}

// ---------------------------------------------------------------------------
// LayerNorm -> fp16 hi output
// ---------------------------------------------------------------------------
__global__ __launch_bounds__(256) void ln_kernel(const float* __restrict__ x,
                                                 __half* __restrict__ yh,
                                                 const float* __restrict__ w,
                                                 const float* __restrict__ b)
{
    __shared__ float red[8];
    int row = blockIdx.x;
    int tid = threadIdx.x;
    const float* xr = x + (size_t)row * DD;
    float4 xv = *(const float4*)&xr[tid * 4];

    float s = xv.x + xv.y + xv.z + xv.w;
    #pragma unroll
    for (int o = 16; o > 0; o >>= 1) s += __shfl_xor_sync(0xffffffffu, s, o);
    if ((tid & 31) == 0) red[tid >> 5] = s;
    __syncthreads();
    float tot = 0.f;
    #pragma unroll
    for (int i = 0; i < 8; i++) tot += red[i];
    float mean = tot * (1.0f / DD);
    __syncthreads();

    float dx0 = xv.x - mean, dx1 = xv.y - mean, dx2 = xv.z - mean, dx3 = xv.w - mean;
    float s2 = dx0*dx0 + dx1*dx1 + dx2*dx2 + dx3*dx3;
    #pragma unroll
    for (int o = 16; o > 0; o >>= 1) s2 += __shfl_xor_sync(0xffffffffu, s2, o);
    if ((tid & 31) == 0) red[tid >> 5] = s2;
    __syncthreads();
    float tot2 = 0.f;
    #pragma unroll
    for (int i = 0; i < 8; i++) tot2 += red[i];
    float inv = rsqrtf(tot2 * (1.0f / DD) + 1e-5f);

    int c = tid * 4;
    float4 wv = *(const float4*)&w[c];
    float4 bv = *(const float4*)&b[c];
    float o0 = dx0 * inv * wv.x + bv.x;
    float o1 = dx1 * inv * wv.y + bv.y;
    float o2 = dx2 * inv * wv.z + bv.z;
    float o3 = dx3 * inv * wv.w + bv.w;
    size_t off = (size_t)row * DD + c;
    *(__half2*)&yh[off]     = __halves2half2(__float2half(o0), __float2half(o1));
    *(__half2*)&yh[off + 2] = __halves2half2(__float2half(o2), __float2half(o3));
}

// ---------------------------------------------------------------------------
// Weight conversion kernels (single fp16, vectorized x4)
// ---------------------------------------------------------------------------
__global__ void conv_kernel(const float* __restrict__ s,
                            __half* __restrict__ h, int n4)
{
    int i = blockIdx.x * blockDim.x + threadIdx.x;
    if (i >= n4) return;
    float4 v = *(const float4*)&s[i * 4];
    *(__half2*)&h[i*4]   = __halves2half2(__float2half(v.x), __float2half(v.y));
    *(__half2*)&h[i*4+2] = __halves2half2(__float2half(v.z), __float2half(v.w));
}

__global__ void pack_qkv_kernel(const float* __restrict__ wq,
                                const float* __restrict__ wk,
                                const float* __restrict__ wv,
                                __half* __restrict__ h)
{
    int i = blockIdx.x * blockDim.x + threadIdx.x;
    const int per_layer4 = QKVD * DD / 4;
    if (i >= LL * per_layer4) return;
    int lyr = i / per_layer4;
    int rem = i - lyr * per_layer4;
    int row = rem >> 8;
    int c4  = rem & 255;
    int which = row >> 10;
    int srow  = row & 1023;
    const float* src = (which == 0) ? wq : ((which == 1) ? wk : wv);
    float4 v = *(const float4*)&src[(size_t)lyr * (DD*DD) + (size_t)srow * DD + c4 * 4];
    size_t o = (size_t)i * 4;
    *(__half2*)&h[o]   = __halves2half2(__float2half(v.x), __float2half(v.y));
    *(__half2*)&h[o+2] = __halves2half2(__float2half(v.z), __float2half(v.w));
}

__global__ void transpose_wo_kernel(const float* __restrict__ wo,
                                    __half* __restrict__ h)
{
    int i = blockIdx.x * blockDim.x + threadIdx.x;
    if (i >= LL * DD * DD) return;
    int lyr = i >> 20;
    int rem = i & ((1 << 20) - 1);
    int nrow = rem >> 10;
    int kcol = rem & 1023;
    h[i] = __float2half(wo[((size_t)lyr << 20) + ((size_t)kcol << 10) + nrow]);
}

// ---------------------------------------------------------------------------
// Launch
// ---------------------------------------------------------------------------
extern "C" void kernel_launch(void* const* d_in, const int* in_sizes, int n_in,
                              void* d_out, int out_size)
{
    const int*   tokens = (const int*)  d_in[0];
    const float* emb    = (const float*)d_in[1];
    const float* ln1_w  = (const float*)d_in[2];
    const float* ln1_b  = (const float*)d_in[3];
    const float* w_q    = (const float*)d_in[4];
    const float* w_k    = (const float*)d_in[5];
    const float* w_v    = (const float*)d_in[6];
    const float* w_o    = (const float*)d_in[7];
    const float* ln2_w  = (const float*)d_in[8];
    const float* ln2_b  = (const float*)d_in[9];
    const float* w1     = (const float*)d_in[10];
    const float* b1     = (const float*)d_in[11];
    const float* w2     = (const float*)d_in[12];
    const float* b2     = (const float*)d_in[13];
    const float* ro_w   = (const float*)d_in[14];
    const float* ro_b   = (const float*)d_in[15];
    float* out = (float*)d_out;

    float *x;
    __half *qkvh, *xnh, *yh, *hh, *xh;
    __half *wqkv, *wo, *w1w, *w2w, *ro;
    cudaGetSymbolAddress((void**)&x,    g_x);
    cudaGetSymbolAddress((void**)&qkvh, g_qkvh);
    cudaGetSymbolAddress((void**)&xnh,  g_xnh);
    cudaGetSymbolAddress((void**)&yh,   g_yh);
    cudaGetSymbolAddress((void**)&hh,   g_hh);
    cudaGetSymbolAddress((void**)&xh,   g_xh);
    cudaGetSymbolAddress((void**)&wqkv, g_wqkv);
    cudaGetSymbolAddress((void**)&wo,   g_wo);
    cudaGetSymbolAddress((void**)&w1w,  g_w1);
    cudaGetSymbolAddress((void**)&w2w,  g_w2);
    cudaGetSymbolAddress((void**)&ro,   g_ro);

    cudaFuncSetAttribute((const void*)gemm_mma<false,false,false,true,false,false>,
                         cudaFuncAttributeMaxDynamicSharedMemorySize, SMEM_B);
    cudaFuncSetAttribute((const void*)gemm_mma<false,false,true,false,false,false>,
                         cudaFuncAttributeMaxDynamicSharedMemorySize, SMEM_B);
    cudaFuncSetAttribute((const void*)gemm_mma<true,true,false,true,false,false>,
                         cudaFuncAttributeMaxDynamicSharedMemorySize, SMEM_B);
    cudaFuncSetAttribute((const void*)gemm_mma<true,false,true,false,false,false>,
                         cudaFuncAttributeMaxDynamicSharedMemorySize, SMEM_B);
    cudaFuncSetAttribute((const void*)gemm_mma<true,false,true,true,false,false>,
                         cudaFuncAttributeMaxDynamicSharedMemorySize, SMEM_B);
    cudaFuncSetAttribute((const void*)gemm_mma<true,false,false,false,false,false>,
                         cudaFuncAttributeMaxDynamicSharedMemorySize, SMEM_B);
    cudaFuncSetAttribute((const void*)attn_mma,
                         cudaFuncAttributeMaxDynamicSharedMemorySize, AT_SMEM);

    // grid: x = M-block (fast), y = N-block (slow)
    const dim3 gQKV(MM/128, QKVD/128);    // 32 x 24
    const dim3 gD  (MM/128, DD/128);      // 32 x 8
    const dim3 gH  (MM/128, HDIM/128);    // 32 x 32
    const dim3 gV  (MM/128, VV/128);      // 32 x 250
    const dim3 gA  (TT/64, BB*HH);        // 32 x 32

    pack_qkv_kernel<<<(LL*QKVD*DD/4 + 255)/256, 256>>>(w_q, w_k, w_v, wqkv);
    embed_ln_kernel<<<MM, 256>>>(tokens, emb, ln1_w, ln1_b, x, xnh);
    transpose_wo_kernel<<<(LL*DD*DD + 255)/256, 256>>>(w_o, wo);
    gemm_mma<false,false,false,true,false,false><<<gQKV, 128, SMEM_B>>>(
        xnh, nullptr, wqkv, nullptr, nullptr, qkvh, nullptr, MM, QKVD, DD);
    conv_kernel<<<(LL*HDIM*DD/4 + 255)/256, 256>>>(w1, w1w, LL*HDIM*DD/4);
    conv_kernel<<<(LL*DD*HDIM/4 + 255)/256, 256>>>(w2, w2w, LL*DD*HDIM/4);
    conv_kernel<<<(VV*DD/4 + 255)/256, 256>>>(ro_w, ro, VV*DD/4);

    for (int l = 0; l < LL; l++) {
        const __half* wqkv_l = wqkv + (size_t)l * QKVD * DD;
        const __half* wo_l   = wo   + (size_t)l * DD * DD;
        const __half* w1_l   = w1w  + (size_t)l * HDIM * DD;
        const __half* w2_l   = w2w  + (size_t)l * DD * HDIM;

        if (l > 0) {
            ln_kernel<<<MM, 256>>>(x, xnh, ln1_w + (size_t)l*DD, ln1_b + (size_t)l*DD);
            gemm_mma<false,false,false,true,false,false><<<gQKV, 128, SMEM_B>>>(
                xnh, nullptr, wqkv_l, nullptr, nullptr, qkvh, nullptr, MM, QKVD, DD);
        }

        attn_mma<<<gA, 128, AT_SMEM>>>(qkvh, yh);

        // x += y @ wo — 1-term A
        gemm_mma<false,false,true,false,false,false><<<gD, 128, SMEM_B>>>(
            yh, nullptr, wo_l, nullptr, x, nullptr, nullptr, MM, DD, DD);

        ln_kernel<<<MM, 256>>>(x, xnh, ln2_w + (size_t)l*DD, ln2_b + (size_t)l*DD);

        // h = relu(xn @ w1 + b1) -> fp16 hi
        gemm_mma<true,true,false,true,false,false><<<gH, 128, SMEM_B>>>(
            xnh, nullptr, w1_l, b1 + (size_t)l*HDIM, nullptr, hh, nullptr, MM, HDIM, DD);

        if (l < LL - 1) {
            gemm_mma<true,false,true,false,false,false><<<gD, 128, SMEM_B>>>(
                hh, nullptr, w2_l, b2 + (size_t)l*DD, x, nullptr, nullptr, MM, DD, HDIM);
        } else {
            gemm_mma<true,false,true,true,false,false><<<gD, 128, SMEM_B>>>(
                hh, nullptr, w2_l, b2 + (size_t)l*DD, x, xh, nullptr, MM, DD, HDIM);
        }
    }

    // readout: out = x @ ro_w^T + ro_b — 1-term A
    gemm_mma<true,false,false,false,false,false><<<gV, 128, SMEM_B>>>(
        xh, nullptr, ro, ro_b, out, nullptr, nullptr, MM, VV, DD);
}

// round 14
// speedup vs baseline: 1.6495x; 1.0052x over previous
#include <cuda_runtime.h>
#include <cuda_fp16.h>
#include <math.h>
#include <stdint.h>

// ---------------------------------------------------------------------------
// Problem constants
// ---------------------------------------------------------------------------
#define BB   2
#define TT   2048
#define DD   1024
#define HH   16
#define HDIM 4096
#define VV   32000
#define LL   4
#define MM   (BB*TT)      // 4096 rows
#define QKVD (3*DD)       // 3072

// ---------------------------------------------------------------------------
// Static device scratch (no allocations allowed)
// ---------------------------------------------------------------------------
__device__ float g_x  [MM*DD];
__device__ __half g_qkvh[MM*QKVD];
__device__ __half g_xnh[MM*DD];
__device__ __half g_yh [MM*DD];
__device__ __half g_hh [MM*HDIM];
__device__ __half g_xh [MM*DD];
__device__ __half g_wqkv[LL*QKVD*DD];
__device__ __half g_wo  [LL*DD*DD];
__device__ __half g_w1  [LL*HDIM*DD];
__device__ __half g_w2  [LL*DD*HDIM];
__device__ __half g_ro  [VV*DD];

// ---------------------------------------------------------------------------
// helpers (base-target PTX only: cp.async, ldmatrix, mma.sync)
// ---------------------------------------------------------------------------
__device__ __forceinline__ uint32_t smem_u32(const void* p) {
    uint32_t a;
    asm("{ .reg .u64 t; cvta.to.shared.u64 t, %1; cvt.u32.u64 %0, t; }"
        : "=r"(a) : "l"(p));
    return a;
}
__device__ __forceinline__ void cp16(uint32_t dst, const void* src) {
    asm volatile("cp.async.cg.shared.global [%0], [%1], 16;" :: "r"(dst), "l"(src));
}
#define CP_COMMIT()  asm volatile("cp.async.commit_group;" ::: "memory")
#define CP_WAIT0()   asm volatile("cp.async.wait_group 0;" ::: "memory")
#define CP_WAIT1()   asm volatile("cp.async.wait_group 1;" ::: "memory")

__device__ __forceinline__ void ldsm4(uint32_t& r0, uint32_t& r1,
                                      uint32_t& r2, uint32_t& r3, uint32_t addr) {
    asm volatile("ldmatrix.sync.aligned.m8n8.x4.shared.b16 {%0,%1,%2,%3}, [%4];"
                 : "=r"(r0), "=r"(r1), "=r"(r2), "=r"(r3) : "r"(addr));
}
__device__ __forceinline__ void ldsm4t(uint32_t& r0, uint32_t& r1,
                                       uint32_t& r2, uint32_t& r3, uint32_t addr) {
    asm volatile("ldmatrix.sync.aligned.m8n8.x4.trans.shared.b16 {%0,%1,%2,%3}, [%4];"
                 : "=r"(r0), "=r"(r1), "=r"(r2), "=r"(r3) : "r"(addr));
}
__device__ __forceinline__ void mma16816(float* d, const uint32_t* a, const uint32_t* b) {
    asm volatile("mma.sync.aligned.m16n8k16.row.col.f32.f16.f16.f32 "
        "{%0,%1,%2,%3}, {%4,%5,%6,%7}, {%8,%9}, {%0,%1,%2,%3};"
        : "+f"(d[0]), "+f"(d[1]), "+f"(d[2]), "+f"(d[3])
        : "r"(a[0]), "r"(a[1]), "r"(a[2]), "r"(a[3]), "r"(b[0]), "r"(b[1]));
}
__device__ __forceinline__ void split2(float v, __half& h, __half& l) {
    h = __float2half(v);
    l = __float2half(v - __half2float(h));
}
__device__ __forceinline__ uint32_t pack2h(__half a, __half b) {
    __half2 hp = __halves2half2(a, b);
    return *(uint32_t*)&hp;
}

// ---------------------------------------------------------------------------
// HMMA GEMM (unchanged R13 config — at the mma.sync rate wall):
// C[M,N] (+)= A[M,K] * B^T, B stored [N,K] fp16. TWOA kept for generality.
// CTA 128x128, 128 threads (4 warps 2x2, 64x64 tiles), KC=32, 3 stages.
// ---------------------------------------------------------------------------
#define STAGES  3
#define KC      32
#define PITCH   80u
#define A_TILE  (128u * PITCH)
#define STAGE_B (3u * A_TILE)
#define SMEM_B  (STAGES * STAGE_B)     // 92160

template<bool BIAS, bool RELU, bool ACCUM, bool SPLIT, bool SPLITLO, bool TWOA>
__global__ __launch_bounds__(128, 2)
void gemm_mma(const __half* __restrict__ Ah, const __half* __restrict__ Al,
              const __half* __restrict__ Bh,
              const float* __restrict__ bias,
              float* __restrict__ C,
              __half* __restrict__ Ch, __half* __restrict__ Cl,
              int M, int N, int K)
{
    extern __shared__ char smem_raw[];
    const uint32_t sb = smem_u32(smem_raw);

    const int tid  = threadIdx.x;
    const int wid  = tid >> 5;
    const int lane = tid & 31;
    const int row0 = blockIdx.x * 128;
    const int col0 = blockIdx.y * 128;
    const int NC   = K / KC;

    auto load_stage = [&](int s) {
        const uint32_t stg = sb + (uint32_t)(s % STAGES) * STAGE_B;
        const int k0 = s * KC;
        const int a_iters = TWOA ? 8 : 4;
        #pragma unroll
        for (int i = 0; i < 8; i++) {
            if (i >= a_iters) break;
            int f = i * 128 + tid;
            int sub = f >> 9;
            int rem = f & 511;
            int r = rem >> 2, c = rem & 3;
            const __half* src = ((sub == 0) ? Ah : Al)
                              + (size_t)(row0 + r) * K + k0 + c * 8;
            cp16(stg + (uint32_t)sub * A_TILE + (uint32_t)r * PITCH + c * 16, src);
        }
        #pragma unroll
        for (int i = 0; i < 4; i++) {
            int f = i * 128 + tid;
            int r = f >> 2, c = f & 3;
            const __half* src = Bh + (size_t)(col0 + r) * K + k0 + c * 8;
            cp16(stg + 2u*A_TILE + (uint32_t)r * PITCH + c * 16, src);
        }
        CP_COMMIT();
    };

    load_stage(0);
    if (NC > 1) load_stage(1);

    const int wm = wid >> 1;
    const int wn = wid & 1;

    float acc[4][8][4];
    #pragma unroll
    for (int a = 0; a < 4; a++)
        #pragma unroll
        for (int b = 0; b < 8; b++)
            #pragma unroll
            for (int c = 0; c < 4; c++) acc[a][b][c] = 0.f;

    for (int i = 0; i < NC; i++) {
        if (i < NC - 1) CP_WAIT1(); else CP_WAIT0();
        __syncthreads();
        if (i + 2 < NC) load_stage(i + 2);

        const uint32_t stg  = sb + (uint32_t)(i % STAGES) * STAGE_B;
        const uint32_t ah_b = stg;
        const uint32_t al_b = stg + A_TILE;
        const uint32_t bh_b = stg + 2u*A_TILE;

        #pragma unroll
        for (int ks = 0; ks < 2; ks++) {
            uint32_t ah[4][4], al[4][4], bf[8][2];
            const uint32_t a_coff = (uint32_t)ks * 32 + ((lane >> 4) << 4);
            #pragma unroll
            for (int mi = 0; mi < 4; mi++) {
                uint32_t r = (uint32_t)(wm * 64 + mi * 16 + (lane & 15));
                ldsm4(ah[mi][0], ah[mi][1], ah[mi][2], ah[mi][3], ah_b + r * PITCH + a_coff);
                if (TWOA)
                    ldsm4(al[mi][0], al[mi][1], al[mi][2], al[mi][3], al_b + r * PITCH + a_coff);
            }
            const uint32_t b_coff = (uint32_t)ks * 32 + (((lane >> 3) & 1) << 4);
            #pragma unroll
            for (int g = 0; g < 4; g++) {
                uint32_t r = (uint32_t)(wn * 64 + g * 16 + (lane & 7) + ((lane >> 4) << 3));
                ldsm4(bf[2*g][0], bf[2*g][1], bf[2*g+1][0], bf[2*g+1][1], bh_b + r * PITCH + b_coff);
            }
            #pragma unroll
            for (int mi = 0; mi < 4; mi++)
                #pragma unroll
                for (int ni = 0; ni < 8; ni++) {
                    mma16816(acc[mi][ni], ah[mi], bf[ni]);
                    if (TWOA) mma16816(acc[mi][ni], al[mi], bf[ni]);
                }
        }
    }

    #pragma unroll
    for (int mi = 0; mi < 4; mi++) {
        #pragma unroll
        for (int rg = 0; rg < 2; rg++) {
            int r = row0 + wm * 64 + mi * 16 + (lane >> 2) + rg * 8;
            #pragma unroll
            for (int ni = 0; ni < 8; ni++) {
                int c = col0 + wn * 64 + ni * 8 + (lane & 3) * 2;
                float v0 = acc[mi][ni][rg * 2 + 0];
                float v1 = acc[mi][ni][rg * 2 + 1];
                if (BIAS)  { v0 += bias[c]; v1 += bias[c + 1]; }
                if (RELU)  { v0 = fmaxf(v0, 0.f); v1 = fmaxf(v1, 0.f); }
                if (ACCUM) {
                    float2 o = *(const float2*)&C[(size_t)r * N + c];
                    v0 += o.x; v1 += o.y;
                }
                if (SPLIT) {
                    if (SPLITLO) {
                        __half h0, l0, h1, l1;
                        split2(v0, h0, l0); split2(v1, h1, l1);
                        *(__half2*)&Ch[(size_t)r * N + c] = __halves2half2(h0, h1);
                        *(__half2*)&Cl[(size_t)r * N + c] = __halves2half2(l0, l1);
                    } else {
                        *(__half2*)&Ch[(size_t)r * N + c] =
                            __halves2half2(__float2half(v0), __float2half(v1));
                    }
                } else {
                    *(float2*)&C[(size_t)r * N + c] = make_float2(v0, v1);
                }
            }
        }
    }
}

// ---------------------------------------------------------------------------
// Tensor-core causal flash attention, single-term fp16, TWO q-tiles per CTA.
// CTA handles q rows [128*qtc, 128*qtc+128) for one (b,h): K/V fragments are
// loaded once and shared by both 64-row q-blocks (halves LDSM/loads/barriers
// per output). Tile0 is masked branch-free via global s>q compare.
// ---------------------------------------------------------------------------
#define AT_PITCH 144u
#define AT_TILE  (64u * AT_PITCH)     // 9216
#define AT_STAGE (2u * AT_TILE)       // 18432: K | V
#define AT_SMEM  (3u * AT_STAGE)      // 55296: 2 KV stages + Q(128 rows)

__global__ __launch_bounds__(128, 2)
void attn_mma(const __half* __restrict__ QKVh, __half* __restrict__ Yh)
{
    extern __shared__ char smem_raw[];
    const uint32_t sb = smem_u32(smem_raw);

    const int tid  = threadIdx.x;
    const int wid  = tid >> 5;
    const int lane = tid & 31;
    const int bh = blockIdx.y;
    const int b  = bh >> 4;
    const int h  = bh & 15;
    const int qtc = (int)(gridDim.x - 1 - blockIdx.x);  // big pairs first
    const int t0 = 2 * qtc;
    const int t1 = t0 + 1;
    const int qrow0 = b * TT + t0 * 64;

    auto load_kv = [&](int st, int stile) {
        const uint32_t stg = sb + (uint32_t)st * AT_STAGE;
        const int srow = b * TT + stile * 64;
        #pragma unroll
        for (int i = 0; i < 8; i++) {
            int f = i * 128 + tid;            // 0..1023
            int sub = f >> 9;                 // 0:K 1:V
            int rem = f & 511;
            int r = rem >> 3, c = rem & 7;
            const __half* src = QKVh + (size_t)(srow + r) * QKVD
                              + DD + sub * DD + h * 64 + c * 8;
            cp16(stg + (uint32_t)sub * AT_TILE + (uint32_t)r * AT_PITCH + c * 16, src);
        }
        CP_COMMIT();
    };

    const uint32_t qstg = sb + 2u * AT_STAGE;
    // prologue: kv tile 0 -> stage 0; Q (128 rows) -> dedicated region
    load_kv(0, 0);
    {
        #pragma unroll
        for (int i = 0; i < 8; i++) {
            int f = i * 128 + tid;            // 0..1023
            int r = f >> 3, c = f & 7;
            const __half* src = QKVh + (size_t)(qrow0 + r) * QKVD + h * 64 + c * 8;
            cp16(qstg + (uint32_t)r * AT_PITCH + c * 16, src);
        }
        CP_COMMIT();
    }
    load_kv(1, 1);                            // t1 >= 1 always
    CP_WAIT1();                               // Q + kv0 done
    __syncthreads();

    uint32_t qf0[4][4], qf1[4][4];
    {
        uint32_t r = (uint32_t)(wid * 16 + (lane & 15));
        #pragma unroll
        for (int ks = 0; ks < 4; ks++) {
            uint32_t coff = (uint32_t)ks * 32 + ((lane >> 4) << 4);
            ldsm4(qf0[ks][0], qf0[ks][1], qf0[ks][2], qf0[ks][3],
                  qstg + r * AT_PITCH + coff);
            ldsm4(qf1[ks][0], qf1[ks][1], qf1[ks][2], qf1[ks][3],
                  qstg + (r + 64u) * AT_PITCH + coff);
        }
    }

    float yacc0[8][4], yacc1[8][4];
    #pragma unroll
    for (int i = 0; i < 8; i++)
        #pragma unroll
        for (int j = 0; j < 4; j++) { yacc0[i][j] = 0.f; yacc1[i][j] = 0.f; }
    float m00 = -1e30f, m01 = -1e30f, l00 = 0.f, l01 = 0.f;   // tile0 rowgrp 0/1
    float m10 = -1e30f, m11 = -1e30f, l10 = 0.f, l11 = 0.f;   // tile1

    const int qg0 = t0 * 64 + wid * 16 + (lane >> 2);   // tile0 rowgroup0 global q
    const int qg1 = qg0 + 64;                           // tile1 rowgroup0 global q

    for (int st = 0; st <= t1; st++) {
        if (st < t1) CP_WAIT1(); else CP_WAIT0();
        __syncthreads();
        const uint32_t stg = sb + (uint32_t)(st & 1) * AT_STAGE;

        float sa0[8][4], sa1[8][4];
        #pragma unroll
        for (int i = 0; i < 8; i++)
            #pragma unroll
            for (int j = 0; j < 4; j++) { sa0[i][j] = 0.f; sa1[i][j] = 0.f; }

        // scores: K fragments shared by both q blocks
        #pragma unroll
        for (int ks = 0; ks < 4; ks++) {
            const uint32_t coff = (uint32_t)ks * 32 + (((lane >> 3) & 1) << 4);
            #pragma unroll
            for (int nbp = 0; nbp < 4; nbp++) {
                uint32_t r = (uint32_t)(nbp * 16 + (lane & 7) + ((lane >> 4) << 3));
                uint32_t kh[4];
                ldsm4(kh[0], kh[1], kh[2], kh[3], stg + r * AT_PITCH + coff);
                mma16816(sa0[2*nbp],   qf0[ks], kh + 0);
                mma16816(sa0[2*nbp+1], qf0[ks], kh + 2);
                mma16816(sa1[2*nbp],   qf1[ks], kh + 0);
                mma16816(sa1[2*nbp+1], qf1[ks], kh + 2);
            }
        }

        #pragma unroll
        for (int ni = 0; ni < 8; ni++)
            #pragma unroll
            for (int j = 0; j < 4; j++) { sa0[ni][j] *= 0.125f; sa1[ni][j] *= 0.125f; }

        // causal masking via global compare (covers diagonal AND fully-masked)
        if (st >= t0) {
            #pragma unroll
            for (int ni = 0; ni < 8; ni++) {
                int sg = st * 64 + ni * 8 + 2 * (lane & 3);
                if (sg     > qg0)     sa0[ni][0] = -1e30f;
                if (sg + 1 > qg0)     sa0[ni][1] = -1e30f;
                if (sg     > qg0 + 8) sa0[ni][2] = -1e30f;
                if (sg + 1 > qg0 + 8) sa0[ni][3] = -1e30f;
                if (st == t1) {
                    if (sg     > qg1)     sa1[ni][0] = -1e30f;
                    if (sg + 1 > qg1)     sa1[ni][1] = -1e30f;
                    if (sg     > qg1 + 8) sa1[ni][2] = -1e30f;
                    if (sg + 1 > qg1 + 8) sa1[ni][3] = -1e30f;
                }
            }
        }

        // ---- softmax (both tiles) ----
        float mxa = -1e30f, mxb = -1e30f, mxc = -1e30f, mxd = -1e30f;
        #pragma unroll
        for (int ni = 0; ni < 8; ni++) {
            mxa = fmaxf(mxa, fmaxf(sa0[ni][0], sa0[ni][1]));
            mxb = fmaxf(mxb, fmaxf(sa0[ni][2], sa0[ni][3]));
            mxc = fmaxf(mxc, fmaxf(sa1[ni][0], sa1[ni][1]));
            mxd = fmaxf(mxd, fmaxf(sa1[ni][2], sa1[ni][3]));
        }
        mxa = fmaxf(mxa, __shfl_xor_sync(0xffffffffu, mxa, 1));
        mxa = fmaxf(mxa, __shfl_xor_sync(0xffffffffu, mxa, 2));
        mxb = fmaxf(mxb, __shfl_xor_sync(0xffffffffu, mxb, 1));
        mxb = fmaxf(mxb, __shfl_xor_sync(0xffffffffu, mxb, 2));
        mxc = fmaxf(mxc, __shfl_xor_sync(0xffffffffu, mxc, 1));
        mxc = fmaxf(mxc, __shfl_xor_sync(0xffffffffu, mxc, 2));
        mxd = fmaxf(mxd, __shfl_xor_sync(0xffffffffu, mxd, 1));
        mxd = fmaxf(mxd, __shfl_xor_sync(0xffffffffu, mxd, 2));

        float n00 = fmaxf(m00, mxa), n01 = fmaxf(m01, mxb);
        float n10 = fmaxf(m10, mxc), n11 = fmaxf(m11, mxd);
        float c00 = __expf(m00 - n00), c01 = __expf(m01 - n01);
        float c10 = __expf(m10 - n10), c11 = __expf(m11 - n11);
        l00 *= c00; l01 *= c01; l10 *= c10; l11 *= c11;
        #pragma unroll
        for (int db = 0; db < 8; db++) {
            yacc0[db][0] *= c00; yacc0[db][1] *= c00;
            yacc0[db][2] *= c01; yacc0[db][3] *= c01;
            yacc1[db][0] *= c10; yacc1[db][1] *= c10;
            yacc1[db][2] *= c11; yacc1[db][3] *= c11;
        }

        uint32_t pf0[4][4], pf1[4][4];
        float sA = 0.f, sB = 0.f, sC = 0.f, sD = 0.f;
        #pragma unroll
        for (int ni = 0; ni < 8; ni++) {
            float p0 = __expf(sa0[ni][0] - n00);
            float p1 = __expf(sa0[ni][1] - n00);
            float p2 = __expf(sa0[ni][2] - n01);
            float p3 = __expf(sa0[ni][3] - n01);
            sA += p0 + p1; sB += p2 + p3;
            float q0 = __expf(sa1[ni][0] - n10);
            float q1 = __expf(sa1[ni][1] - n10);
            float q2 = __expf(sa1[ni][2] - n11);
            float q3 = __expf(sa1[ni][3] - n11);
            sC += q0 + q1; sD += q2 + q3;
            int ks = ni >> 1;
            uint32_t a0 = pack2h(__float2half(p0), __float2half(p1));
            uint32_t a1 = pack2h(__float2half(p2), __float2half(p3));
            uint32_t b0 = pack2h(__float2half(q0), __float2half(q1));
            uint32_t b1 = pack2h(__float2half(q2), __float2half(q3));
            if ((ni & 1) == 0) {
                pf0[ks][0] = a0; pf0[ks][1] = a1;
                pf1[ks][0] = b0; pf1[ks][1] = b1;
            } else {
                pf0[ks][2] = a0; pf0[ks][3] = a1;
                pf1[ks][2] = b0; pf1[ks][3] = b1;
            }
        }
        sA += __shfl_xor_sync(0xffffffffu, sA, 1);
        sA += __shfl_xor_sync(0xffffffffu, sA, 2);
        sB += __shfl_xor_sync(0xffffffffu, sB, 1);
        sB += __shfl_xor_sync(0xffffffffu, sB, 2);
        sC += __shfl_xor_sync(0xffffffffu, sC, 1);
        sC += __shfl_xor_sync(0xffffffffu, sC, 2);
        sD += __shfl_xor_sync(0xffffffffu, sD, 1);
        sD += __shfl_xor_sync(0xffffffffu, sD, 2);
        l00 += sA; l01 += sB; l10 += sC; l11 += sD;
        m00 = n00; m01 = n01; m10 = n10; m11 = n11;

        // ---- PV: V fragments shared by both q blocks ----
        const uint32_t vb = stg + AT_TILE;
        #pragma unroll
        for (int ks = 0; ks < 4; ks++) {
            #pragma unroll
            for (int dbp = 0; dbp < 4; dbp++) {
                uint32_t raddr = (uint32_t)(ks * 16 + (lane & 15)) * AT_PITCH
                               + (uint32_t)dbp * 32 + ((lane >> 4) << 4);
                uint32_t vh[4];
                ldsm4t(vh[0], vh[1], vh[2], vh[3], vb + raddr);
                mma16816(yacc0[2*dbp],   pf0[ks], vh + 0);
                mma16816(yacc0[2*dbp+1], pf0[ks], vh + 2);
                mma16816(yacc1[2*dbp],   pf1[ks], vh + 0);
                mma16816(yacc1[2*dbp+1], pf1[ks], vh + 2);
            }
        }

        if (st + 2 <= t1) {
            __syncthreads();
            load_kv(st & 1, st + 2);
        }
    }

    // ---- epilogue ----
    float i00 = 1.f / l00, i01 = 1.f / l01, i10 = 1.f / l10, i11 = 1.f / l11;
    int r0 = qrow0 + wid * 16 + (lane >> 2);
    size_t b00 = (size_t)r0 * DD + h * 64;
    size_t b01 = b00 + (size_t)8 * DD;
    size_t b10 = b00 + (size_t)64 * DD;
    size_t b11 = b10 + (size_t)8 * DD;
    #pragma unroll
    for (int db = 0; db < 8; db++) {
        int cc = db * 8 + 2 * (lane & 3);
        *(__half2*)&Yh[b00 + cc] = __halves2half2(
            __float2half(yacc0[db][0] * i00), __float2half(yacc0[db][1] * i00));
        *(__half2*)&Yh[b01 + cc] = __halves2half2(
            __float2half(yacc0[db][2] * i01), __float2half(yacc0[db][3] * i01));
        *(__half2*)&Yh[b10 + cc] = __halves2half2(
            __float2half(yacc1[db][0] * i10), __float2half(yacc1[db][1] * i10));
        *(__half2*)&Yh[b11 + cc] = __halves2half2(
            __float2half(yacc1[db][2] * i11), __float2half(yacc1[db][3] * i11));
    }
}

// ---------------------------------------------------------------------------
// Fused embedding + positional encoding + LayerNorm(ln1, layer 0) -> fp16 hi.
// ---------------------------------------------------------------------------
__global__ __launch_bounds__(256) void embed_ln_kernel(const int* __restrict__ tokens,
                                                       const float* __restrict__ emb,
                                                       const float* __restrict__ w,
                                                       const float* __restrict__ b,
                                                       float* __restrict__ x,
                                                       __half* __restrict__ yh)
{
    __shared__ float red[8];
    int row = blockIdx.x;
    int tid = threadIdx.x;
    int bb  = row >> 11;
    int t   = row & (TT - 1);
    int tok = (t == 0) ? 0 : tokens[bb * TT + t - 1];

    int c = tid * 4;
    float v[4];
    #pragma unroll
    for (int j = 0; j < 4; j++) {
        int d = c + j;
        int k = d & 1;
        double e = (double)(d - k) / (double)DD;
        float freq = (float)exp(-e * 11.512925464970229);
        float arg = (float)t * freq + 1.5707963267948966f * (float)k;
        v[j] = emb[(size_t)tok * DD + d] + sinf(arg);
    }
    *(float4*)&x[(size_t)row * DD + c] = make_float4(v[0], v[1], v[2], v[3]);

    float s = v[0] + v[1] + v[2] + v[3];
    #pragma unroll
    for (int o = 16; o > 0; o >>= 1) s += __shfl_xor_sync(0xffffffffu, s, o);
    if ((tid & 31) == 0) red[tid >> 5] = s;
    __syncthreads();
    float tot = 0.f;
    #pragma unroll
    for (int i = 0; i < 8; i++) tot += red[i];
    float mean = tot * (1.0f / DD);
    __syncthreads();

    float dx0 = v[0]-mean, dx1 = v[1]-mean, dx2 = v[2]-mean, dx3 = v[3]-mean;
    float s2 = dx0*dx0 + dx1*dx1 + dx2*dx2 + dx3*dx3;
    #pragma unroll
    for (int o = 16; o > 0; o >>= 1) s2 += __shfl_xor_sync(0xffffffffu, s2, o);
    if ((tid & 31) == 0) red[tid >> 5] = s2;
    __syncthreads();
    float tot2 = 0.f;
    #pragma unroll
    for (int i = 0; i < 8; i++) tot2 += red[i];
    float inv = rsqrtf(tot2 * (1.0f / DD) + 1e-5f);

    float4 wv = *(const float4*)&w[c];
    float4 bv = *(const float4*)&b[c];
    float o0 = dx0 * inv * wv.x + bv.x;
    float o1 = dx1 * inv * wv.y + bv.y;
    float o2 = dx2 * inv * wv.z + bv.z;
    float o3 = dx3 * inv * wv.w + bv.w;
    size_t off = (size_t)row * DD + c;
    *(__half2*)&yh[off]     = __halves2half2(__float2half(o0), __float2half(o1));
    *(__half2*)&yh[off + 2] = __halves2half2(__float2half(o2), __float2half(o3));
}

// ---------------------------------------------------------------------------
// LayerNorm -> fp16 hi output
// ---------------------------------------------------------------------------
__global__ __launch_bounds__(256) void ln_kernel(const float* __restrict__ x,
                                                 __half* __restrict__ yh,
                                                 const float* __restrict__ w,
                                                 const float* __restrict__ b)
{
    __shared__ float red[8];
    int row = blockIdx.x;
    int tid = threadIdx.x;
    const float* xr = x + (size_t)row * DD;
    float4 xv = *(const float4*)&xr[tid * 4];

    float s = xv.x + xv.y + xv.z + xv.w;
    #pragma unroll
    for (int o = 16; o > 0; o >>= 1) s += __shfl_xor_sync(0xffffffffu, s, o);
    if ((tid & 31) == 0) red[tid >> 5] = s;
    __syncthreads();
    float tot = 0.f;
    #pragma unroll
    for (int i = 0; i < 8; i++) tot += red[i];
    float mean = tot * (1.0f / DD);
    __syncthreads();

    float dx0 = xv.x - mean, dx1 = xv.y - mean, dx2 = xv.z - mean, dx3 = xv.w - mean;
    float s2 = dx0*dx0 + dx1*dx1 + dx2*dx2 + dx3*dx3;
    #pragma unroll
    for (int o = 16; o > 0; o >>= 1) s2 += __shfl_xor_sync(0xffffffffu, s2, o);
    if ((tid & 31) == 0) red[tid >> 5] = s2;
    __syncthreads();
    float tot2 = 0.f;
    #pragma unroll
    for (int i = 0; i < 8; i++) tot2 += red[i];
    float inv = rsqrtf(tot2 * (1.0f / DD) + 1e-5f);

    int c = tid * 4;
    float4 wv = *(const float4*)&w[c];
    float4 bv = *(const float4*)&b[c];
    float o0 = dx0 * inv * wv.x + bv.x;
    float o1 = dx1 * inv * wv.y + bv.y;
    float o2 = dx2 * inv * wv.z + bv.z;
    float o3 = dx3 * inv * wv.w + bv.w;
    size_t off = (size_t)row * DD + c;
    *(__half2*)&yh[off]     = __halves2half2(__float2half(o0), __float2half(o1));
    *(__half2*)&yh[off + 2] = __halves2half2(__float2half(o2), __float2half(o3));
}

// ---------------------------------------------------------------------------
// Weight conversion kernels (single fp16, vectorized x4)
// ---------------------------------------------------------------------------
__global__ void conv_kernel(const float* __restrict__ s,
                            __half* __restrict__ h, int n4)
{
    int i = blockIdx.x * blockDim.x + threadIdx.x;
    if (i >= n4) return;
    float4 v = *(const float4*)&s[i * 4];
    *(__half2*)&h[i*4]   = __halves2half2(__float2half(v.x), __float2half(v.y));
    *(__half2*)&h[i*4+2] = __halves2half2(__float2half(v.z), __float2half(v.w));
}

__global__ void pack_qkv_kernel(const float* __restrict__ wq,
                                const float* __restrict__ wk,
                                const float* __restrict__ wv,
                                __half* __restrict__ h)
{
    int i = blockIdx.x * blockDim.x + threadIdx.x;
    const int per_layer4 = QKVD * DD / 4;
    if (i >= LL * per_layer4) return;
    int lyr = i / per_layer4;
    int rem = i - lyr * per_layer4;
    int row = rem >> 8;
    int c4  = rem & 255;
    int which = row >> 10;
    int srow  = row & 1023;
    const float* src = (which == 0) ? wq : ((which == 1) ? wk : wv);
    float4 v = *(const float4*)&src[(size_t)lyr * (DD*DD) + (size_t)srow * DD + c4 * 4];
    size_t o = (size_t)i * 4;
    *(__half2*)&h[o]   = __halves2half2(__float2half(v.x), __float2half(v.y));
    *(__half2*)&h[o+2] = __halves2half2(__float2half(v.z), __float2half(v.w));
}

__global__ void transpose_wo_kernel(const float* __restrict__ wo,
                                    __half* __restrict__ h)
{
    int i = blockIdx.x * blockDim.x + threadIdx.x;
    if (i >= LL * DD * DD) return;
    int lyr = i >> 20;
    int rem = i & ((1 << 20) - 1);
    int nrow = rem >> 10;
    int kcol = rem & 1023;
    h[i] = __float2half(wo[((size_t)lyr << 20) + ((size_t)kcol << 10) + nrow]);
}

// ---------------------------------------------------------------------------
// Launch
// ---------------------------------------------------------------------------
extern "C" void kernel_launch(void* const* d_in, const int* in_sizes, int n_in,
                              void* d_out, int out_size)
{
    const int*   tokens = (const int*)  d_in[0];
    const float* emb    = (const float*)d_in[1];
    const float* ln1_w  = (const float*)d_in[2];
    const float* ln1_b  = (const float*)d_in[3];
    const float* w_q    = (const float*)d_in[4];
    const float* w_k    = (const float*)d_in[5];
    const float* w_v    = (const float*)d_in[6];
    const float* w_o    = (const float*)d_in[7];
    const float* ln2_w  = (const float*)d_in[8];
    const float* ln2_b  = (const float*)d_in[9];
    const float* w1     = (const float*)d_in[10];
    const float* b1     = (const float*)d_in[11];
    const float* w2     = (const float*)d_in[12];
    const float* b2     = (const float*)d_in[13];
    const float* ro_w   = (const float*)d_in[14];
    const float* ro_b   = (const float*)d_in[15];
    float* out = (float*)d_out;

    float *x;
    __half *qkvh, *xnh, *yh, *hh, *xh;
    __half *wqkv, *wo, *w1w, *w2w, *ro;
    cudaGetSymbolAddress((void**)&x,    g_x);
    cudaGetSymbolAddress((void**)&qkvh, g_qkvh);
    cudaGetSymbolAddress((void**)&xnh,  g_xnh);
    cudaGetSymbolAddress((void**)&yh,   g_yh);
    cudaGetSymbolAddress((void**)&hh,   g_hh);
    cudaGetSymbolAddress((void**)&xh,   g_xh);
    cudaGetSymbolAddress((void**)&wqkv, g_wqkv);
    cudaGetSymbolAddress((void**)&wo,   g_wo);
    cudaGetSymbolAddress((void**)&w1w,  g_w1);
    cudaGetSymbolAddress((void**)&w2w,  g_w2);
    cudaGetSymbolAddress((void**)&ro,   g_ro);

    cudaFuncSetAttribute((const void*)gemm_mma<false,false,false,true,false,false>,
                         cudaFuncAttributeMaxDynamicSharedMemorySize, SMEM_B);
    cudaFuncSetAttribute((const void*)gemm_mma<false,false,true,false,false,false>,
                         cudaFuncAttributeMaxDynamicSharedMemorySize, SMEM_B);
    cudaFuncSetAttribute((const void*)gemm_mma<true,true,false,true,false,false>,
                         cudaFuncAttributeMaxDynamicSharedMemorySize, SMEM_B);
    cudaFuncSetAttribute((const void*)gemm_mma<true,false,true,false,false,false>,
                         cudaFuncAttributeMaxDynamicSharedMemorySize, SMEM_B);
    cudaFuncSetAttribute((const void*)gemm_mma<true,false,true,true,false,false>,
                         cudaFuncAttributeMaxDynamicSharedMemorySize, SMEM_B);
    cudaFuncSetAttribute((const void*)gemm_mma<true,false,false,false,false,false>,
                         cudaFuncAttributeMaxDynamicSharedMemorySize, SMEM_B);
    cudaFuncSetAttribute((const void*)attn_mma,
                         cudaFuncAttributeMaxDynamicSharedMemorySize, AT_SMEM);

    // grid: x = M-block (fast), y = N-block (slow)
    const dim3 gQKV(MM/128, QKVD/128);    // 32 x 24
    const dim3 gD  (MM/128, DD/128);      // 32 x 8
    const dim3 gH  (MM/128, HDIM/128);    // 32 x 32
    const dim3 gV  (MM/128, VV/128);      // 32 x 250
    const dim3 gA  (TT/128, BB*HH);       // 16 x 32  (2 q-tiles per CTA)

    pack_qkv_kernel<<<(LL*QKVD*DD/4 + 255)/256, 256>>>(w_q, w_k, w_v, wqkv);
    embed_ln_kernel<<<MM, 256>>>(tokens, emb, ln1_w, ln1_b, x, xnh);
    transpose_wo_kernel<<<(LL*DD*DD + 255)/256, 256>>>(w_o, wo);
    gemm_mma<false,false,false,true,false,false><<<gQKV, 128, SMEM_B>>>(
        xnh, nullptr, wqkv, nullptr, nullptr, qkvh, nullptr, MM, QKVD, DD);
    conv_kernel<<<(LL*HDIM*DD/4 + 255)/256, 256>>>(w1, w1w, LL*HDIM*DD/4);
    conv_kernel<<<(LL*DD*HDIM/4 + 255)/256, 256>>>(w2, w2w, LL*DD*HDIM/4);
    conv_kernel<<<(VV*DD/4 + 255)/256, 256>>>(ro_w, ro, VV*DD/4);

    for (int l = 0; l < LL; l++) {
        const __half* wqkv_l = wqkv + (size_t)l * QKVD * DD;
        const __half* wo_l   = wo   + (size_t)l * DD * DD;
        const __half* w1_l   = w1w  + (size_t)l * HDIM * DD;
        const __half* w2_l   = w2w  + (size_t)l * DD * HDIM;

        if (l > 0) {
            ln_kernel<<<MM, 256>>>(x, xnh, ln1_w + (size_t)l*DD, ln1_b + (size_t)l*DD);
            gemm_mma<false,false,false,true,false,false><<<gQKV, 128, SMEM_B>>>(
                xnh, nullptr, wqkv_l, nullptr, nullptr, qkvh, nullptr, MM, QKVD, DD);
        }

        attn_mma<<<gA, 128, AT_SMEM>>>(qkvh, yh);

        gemm_mma<false,false,true,false,false,false><<<gD, 128, SMEM_B>>>(
            yh, nullptr, wo_l, nullptr, x, nullptr, nullptr, MM, DD, DD);

        ln_kernel<<<MM, 256>>>(x, xnh, ln2_w + (size_t)l*DD, ln2_b + (size_t)l*DD);

        gemm_mma<true,true,false,true,false,false><<<gH, 128, SMEM_B>>>(
            xnh, nullptr, w1_l, b1 + (size_t)l*HDIM, nullptr, hh, nullptr, MM, HDIM, DD);

        if (l < LL - 1) {
            gemm_mma<true,false,true,false,false,false><<<gD, 128, SMEM_B>>>(
                hh, nullptr, w2_l, b2 + (size_t)l*DD, x, nullptr, nullptr, MM, DD, HDIM);
        } else {
            gemm_mma<true,false,true,true,false,false><<<gD, 128, SMEM_B>>>(
                hh, nullptr, w2_l, b2 + (size_t)l*DD, x, xh, nullptr, MM, DD, HDIM);
        }
    }

    // readout: out = x @ ro_w^T + ro_b
    gemm_mma<true,false,false,false,false,false><<<gV, 128, SMEM_B>>>(
        xh, nullptr, ro, ro_b, out, nullptr, nullptr, MM, VV, DD);
}